// round 8
// baseline (speedup 1.0000x reference)
#include <cuda_runtime.h>
#include <math.h>

#define NL 6
#define B  8
#define T  4
#define L  2048
#define H  16
#define D  64
#define E  1024
#define FF 4096
#define INDIM 32
#define NTOK 32

#define CACHE_F4 50331648LL            // NL*2*B*L*E/4

// -------- scratch (device globals) --------
__device__ float g_x    [NTOK * E];
__device__ float g_xn   [NTOK * E];
__device__ float g_q    [NTOK * E];
__device__ float g_attn [NTOK * E];
__device__ float g_part [262144];      // l1 partials (2 x 32 x 4096)
__device__ float g_part2[262144];      // qkv (2x32x3072) / op / l2 (8x32x1024)
__device__ float g_seq  [NTOK * INDIM];
__device__ float g_po   [B * H * 4 * T * D];
__device__ float g_m    [B * H * 4 * T];
__device__ float g_l    [B * H * 4 * T];

// -------- f32x2 helpers --------
__device__ __forceinline__ unsigned long long pk2(float lo, float hi) {
    unsigned long long r;
    asm("mov.b64 %0, {%1, %2};" : "=l"(r) : "f"(lo), "f"(hi));
    return r;
}
__device__ __forceinline__ void fma2(unsigned long long& d,
                                     unsigned long long a,
                                     unsigned long long b) {
    asm("fma.rn.f32x2 %0, %1, %2, %3;" : "=l"(d) : "l"(a), "l"(b), "l"(d));
}
__device__ __forceinline__ float2 upk(unsigned long long v) {
    float2 f;
    asm("mov.b64 {%0, %1}, %2;" : "=f"(f.x), "=f"(f.y) : "l"(v));
    return f;
}
__device__ __forceinline__ float gelu1(float v) {
    return 0.5f * v * (1.0f + erff(v * 0.70710678118654752f));
}

// -------- bulk cache copy: small persistent grid, co-resides with chain --------
__global__ __launch_bounds__(256, 8) void cache_copy_kernel(
    const float4* __restrict__ in, float4* __restrict__ out,
    const int* __restrict__ allpos)
{
    long long stride = (long long)gridDim.x * 256;
    #pragma unroll 2
    for (long long i = (long long)blockIdx.x * 256 + threadIdx.x; i < CACHE_F4; i += stride) {
        unsigned slot = ((unsigned)(i >> 8)) & 2047u;
        unsigned b    = ((unsigned)(i >> 19)) & 7u;
        unsigned l    = ((unsigned)(i >> 22)) >> 1;
        int p = allpos[l * 8 + b];
        if ((unsigned)((int)slot - p) < (unsigned)T) continue;   // new slot: scatter owns
        float4 v = in[i];
        v.x = isnan(v.x) ? 0.0f : v.x;
        v.y = isnan(v.y) ? 0.0f : v.y;
        v.z = isnan(v.z) ? 0.0f : v.z;
        v.w = isnan(v.w) ? 0.0f : v.w;
        out[i] = v;
    }
}

// -------- prep seq (NaN->bos) + new positions --------
__global__ void prep_pos_kernel(const float* __restrict__ seq,
                                const float* __restrict__ bos,
                                const int* __restrict__ positions,
                                float* __restrict__ out_seq,
                                float* __restrict__ out_pos)
{
    if (blockIdx.x < 4) {
        int i = blockIdx.x * 256 + threadIdx.x;
        float v = seq[i];
        out_seq[i] = isnan(v) ? bos[i & (INDIM - 1)] : v;
    } else {
        int i = threadIdx.x;
        if (i < NL * B) out_pos[i] = (float)(positions[i] + T);
    }
}

// ======== GEMM: Y[32,N] = X[32,K] @ W[N,K]^T, f32x2, 2-deep prefetch ========
// GELUX=1: X is l1 split-K partial pair (rows r and r+32, stride K); gelu(p0+p1).
// KSPLIT==1: direct store to Y; else partials to part.
template<int GELUX, int KSPLIT>
__global__ void gemv64_kernel(const float* __restrict__ X,
                              const float* __restrict__ W,
                              float* __restrict__ Y,
                              float* __restrict__ part,
                              int K, int N)
{
    __shared__ alignas(16) float Ws[64][36];
    __shared__ alignas(16) unsigned long long XsP[16][33];

    const int t    = threadIdx.x;
    const int lane = t & 31;
    const int c0   = (t >> 5) * 8;
    const int n0   = blockIdx.x * 64;
    const int Kc   = K / KSPLIT;
    const int kbase = blockIdx.y * Kc;
    const int nch  = Kc >> 5;

    const int xrow = t >> 3, xk = (t & 7) * 4;
    const int wrow = t >> 2, wk = (t & 3) * 8;

    const float4* xg  = (const float4*)(X + (size_t)xrow * K + kbase + xk);
    const float4* x2g = (const float4*)(X + (size_t)(32 + xrow) * K + kbase + xk);
    const float4* wg  = (const float4*)(W + (size_t)(n0 + wrow) * K + kbase + wk);

    float4 xa = xg[0], xa2, xb, xb2, wa0 = wg[0], wa1 = wg[1], wb0, wb1;
    if (GELUX) xa2 = x2g[0];
    if (nch > 1) {
        xb = xg[8]; wb0 = wg[8]; wb1 = wg[9];
        if (GELUX) xb2 = x2g[8];
    }

    unsigned long long acc[8];
    #pragma unroll
    for (int c = 0; c < 8; c++) acc[c] = 0ULL;

    for (int ch = 0; ch < nch; ch++) {
        float4 xs, xs2, ws0, ws1;
        if ((ch & 1) == 0) { xs = xa; xs2 = xa2; ws0 = wa0; ws1 = wa1; }
        else               { xs = xb; xs2 = xb2; ws0 = wb0; ws1 = wb1; }
        if (GELUX) {
            xs.x = gelu1(xs.x + xs2.x);
            xs.y = gelu1(xs.y + xs2.y);
            xs.z = gelu1(xs.z + xs2.z);
            xs.w = gelu1(xs.w + xs2.w);
        }
        XsP[(xk >> 1)    ][xrow] = pk2(xs.x, xs.y);
        XsP[(xk >> 1) + 1][xrow] = pk2(xs.z, xs.w);
        *(float4*)&Ws[wrow][wk]     = ws0;
        *(float4*)&Ws[wrow][wk + 4] = ws1;
        __syncthreads();

        if (ch + 2 < nch) {
            int off = (ch + 2) * 8;
            if ((ch & 1) == 0) {
                xa = xg[off]; wa0 = wg[off]; wa1 = wg[off + 1];
                if (GELUX) xa2 = x2g[off];
            } else {
                xb = xg[off]; wb0 = wg[off]; wb1 = wg[off + 1];
                if (GELUX) xb2 = x2g[off];
            }
        }

        #pragma unroll
        for (int k2 = 0; k2 < 16; k2 += 2) {
            unsigned long long x0 = XsP[k2][lane];
            unsigned long long x1 = XsP[k2 + 1][lane];
            #pragma unroll
            for (int c = 0; c < 8; c++) {
                longlong2 w = *(const longlong2*)&Ws[c0 + c][k2 * 2];
                fma2(acc[c], x0, (unsigned long long)w.x);
                fma2(acc[c], x1, (unsigned long long)w.y);
            }
        }
        __syncthreads();
    }

    if (KSPLIT == 1) {
        #pragma unroll
        for (int c = 0; c < 8; c++) {
            float2 p = upk(acc[c]);
            Y[(size_t)lane * N + n0 + c0 + c] = p.x + p.y;
        }
    } else {
        float* pp = part + ((size_t)blockIdx.y * 32 + lane) * N + n0 + c0;
        #pragma unroll
        for (int c = 0; c < 8; c++) {
            float2 p = upk(acc[c]);
            pp[c] = p.x + p.y;
        }
    }
}

// -------- fused qkv split-K(2) reduce + RoPE + cache scatter --------
__global__ void reduce_rope_kernel(const float* __restrict__ part,
                                   const int* __restrict__ pos_l,
                                   float* __restrict__ qout,
                                   float* __restrict__ kcache,
                                   float* __restrict__ vcache)
{
    int id = blockIdx.x * 256 + threadIdx.x;  // 49152 pairs
    int tok = id / 1536;
    int f   = (id - tok * 1536) * 2;
    float s0 = part[(size_t)tok * 3072 + f]     + part[(size_t)(32 + tok) * 3072 + f];
    float s1 = part[(size_t)tok * 3072 + f + 1] + part[(size_t)(32 + tok) * 3072 + f + 1];
    int b = tok >> 2, t = tok & 3;
    int pos = pos_l[b];
    if (f < E) {
        int j = (f & 63) >> 1;
        float freq = __expf(-(float)j * (logf(10000.0f) / 32.0f));
        float sn, cs;
        sincosf((float)(pos + t) * freq, &sn, &cs);
        qout[(size_t)tok * E + f]     = s0 * cs - s1 * sn;
        qout[(size_t)tok * E + f + 1] = s0 * sn + s1 * cs;
    } else if (f < 2 * E) {
        int fk = f - E;
        int j = (fk & 63) >> 1;
        float freq = __expf(-(float)j * (logf(10000.0f) / 32.0f));
        float sn, cs;
        sincosf((float)(pos + t) * freq, &sn, &cs);
        int slot = (pos + t) % L;
        size_t off = ((size_t)b * L + slot) * E + fk;
        kcache[off]     = s0 * cs - s1 * sn;
        kcache[off + 1] = s0 * sn + s1 * cs;
    } else {
        int fv = f - 2 * E;
        int slot = (pos + t) % L;
        size_t off = ((size_t)b * L + slot) * E + fv;
        vcache[off]     = s0;
        vcache[off + 1] = s1;
    }
}

// -------- LayerNorm (layer-0 entry) --------
__global__ void ln_kernel(const float* __restrict__ X,
                          const float* __restrict__ w,
                          const float* __restrict__ b,
                          float* __restrict__ Y)
{
    int tok = blockIdx.x;
    int tid = threadIdx.x;
    const float* x = X + (size_t)tok * E;
    float v[4];
    #pragma unroll
    for (int j = 0; j < 4; j++) v[j] = x[tid + 256 * j];
    float s = v[0] + v[1] + v[2] + v[3];
    #pragma unroll
    for (int o = 16; o > 0; o >>= 1) s += __shfl_xor_sync(0xffffffffu, s, o);
    __shared__ float ws[8];
    if ((tid & 31) == 0) ws[tid >> 5] = s;
    __syncthreads();
    float mean = (ws[0]+ws[1]+ws[2]+ws[3]+ws[4]+ws[5]+ws[6]+ws[7]) * (1.0f / E);
    float s2 = 0.f;
    #pragma unroll
    for (int j = 0; j < 4; j++) { float d = v[j] - mean; s2 += d * d; }
    #pragma unroll
    for (int o = 16; o > 0; o >>= 1) s2 += __shfl_xor_sync(0xffffffffu, s2, o);
    __syncthreads();
    if ((tid & 31) == 0) ws[tid >> 5] = s2;
    __syncthreads();
    float var = (ws[0]+ws[1]+ws[2]+ws[3]+ws[4]+ws[5]+ws[6]+ws[7]) * (1.0f / E);
    float r = rsqrtf(var + 1e-5f);
    #pragma unroll
    for (int j = 0; j < 4; j++) {
        int idx = tid + 256 * j;
        Y[(size_t)tok * E + idx] = (v[j] - mean) * r * w[idx] + b[idx];
    }
}

// -------- fused: x += sum(8 partials); xn = LN(x) --------
__global__ void reduce_ln_kernel(const float* __restrict__ part,
                                 float* __restrict__ x,
                                 const float* __restrict__ w,
                                 const float* __restrict__ b,
                                 float* __restrict__ xn)
{
    int tok = blockIdx.x;
    int tid = threadIdx.x;
    float v[4];
    #pragma unroll
    for (int j = 0; j < 4; j++) {
        int idx = tid + 256 * j;
        float p = 0.f;
        #pragma unroll
        for (int k = 0; k < 8; k++) p += part[((size_t)(k * 32 + tok)) * E + idx];
        float xv = x[(size_t)tok * E + idx] + p;
        x[(size_t)tok * E + idx] = xv;
        v[j] = xv;
    }
    float s = v[0] + v[1] + v[2] + v[3];
    #pragma unroll
    for (int o = 16; o > 0; o >>= 1) s += __shfl_xor_sync(0xffffffffu, s, o);
    __shared__ float ws[8];
    if ((tid & 31) == 0) ws[tid >> 5] = s;
    __syncthreads();
    float mean = (ws[0]+ws[1]+ws[2]+ws[3]+ws[4]+ws[5]+ws[6]+ws[7]) * (1.0f / E);
    float s2 = 0.f;
    #pragma unroll
    for (int j = 0; j < 4; j++) { float d = v[j] - mean; s2 += d * d; }
    #pragma unroll
    for (int o = 16; o > 0; o >>= 1) s2 += __shfl_xor_sync(0xffffffffu, s2, o);
    __syncthreads();
    if ((tid & 31) == 0) ws[tid >> 5] = s2;
    __syncthreads();
    float var = (ws[0]+ws[1]+ws[2]+ws[3]+ws[4]+ws[5]+ws[6]+ws[7]) * (1.0f / E);
    float r = rsqrtf(var + 1e-5f);
    #pragma unroll
    for (int j = 0; j < 4; j++) {
        int idx = tid + 256 * j;
        xn[(size_t)tok * E + idx] = (v[j] - mean) * r * w[idx] + b[idx];
    }
}

// -------- fused: x += partials; out_x = LN(x); eos dot --------
__global__ void reduce_ln_eos_kernel(const float* __restrict__ part,
                                     float* __restrict__ x,
                                     const float* __restrict__ w,
                                     const float* __restrict__ b,
                                     const float* __restrict__ ew,
                                     const float* __restrict__ eb,
                                     float* __restrict__ Y,
                                     float* __restrict__ out_eos)
{
    int tok = blockIdx.x;
    int tid = threadIdx.x;
    float v[4];
    #pragma unroll
    for (int j = 0; j < 4; j++) {
        int idx = tid + 256 * j;
        float p = 0.f;
        #pragma unroll
        for (int k = 0; k < 8; k++) p += part[((size_t)(k * 32 + tok)) * E + idx];
        v[j] = x[(size_t)tok * E + idx] + p;
    }
    float s = v[0] + v[1] + v[2] + v[3];
    #pragma unroll
    for (int o = 16; o > 0; o >>= 1) s += __shfl_xor_sync(0xffffffffu, s, o);
    __shared__ float ws[8];
    if ((tid & 31) == 0) ws[tid >> 5] = s;
    __syncthreads();
    float mean = (ws[0]+ws[1]+ws[2]+ws[3]+ws[4]+ws[5]+ws[6]+ws[7]) * (1.0f / E);
    float s2 = 0.f;
    #pragma unroll
    for (int j = 0; j < 4; j++) { float d = v[j] - mean; s2 += d * d; }
    #pragma unroll
    for (int o = 16; o > 0; o >>= 1) s2 += __shfl_xor_sync(0xffffffffu, s2, o);
    __syncthreads();
    if ((tid & 31) == 0) ws[tid >> 5] = s2;
    __syncthreads();
    float var = (ws[0]+ws[1]+ws[2]+ws[3]+ws[4]+ws[5]+ws[6]+ws[7]) * (1.0f / E);
    float r = rsqrtf(var + 1e-5f);
    float ed = 0.f;
    #pragma unroll
    for (int j = 0; j < 4; j++) {
        int idx = tid + 256 * j;
        float y = (v[j] - mean) * r * w[idx] + b[idx];
        Y[(size_t)tok * E + idx] = y;
        ed += y * ew[idx];
    }
    #pragma unroll
    for (int o = 16; o > 0; o >>= 1) ed += __shfl_xor_sync(0xffffffffu, ed, o);
    __syncthreads();
    if ((tid & 31) == 0) ws[tid >> 5] = ed;
    __syncthreads();
    if (tid == 0)
        out_eos[tok] = ws[0]+ws[1]+ws[2]+ws[3]+ws[4]+ws[5]+ws[6]+ws[7] + eb[0];
}

// -------- Attention partial: grid 512, old K/V from input cache --------
#define CMAX 260
__global__ void attn_part_kernel(const float* __restrict__ q,
                                 const float* __restrict__ kin,
                                 const float* __restrict__ vin,
                                 const float* __restrict__ kout,
                                 const float* __restrict__ vout,
                                 const int* __restrict__ pos_l,
                                 float* __restrict__ po,
                                 float* __restrict__ gm,
                                 float* __restrict__ gl)
{
    __shared__ float qs[4][64];
    __shared__ float sc[4][CMAX];
    __shared__ float red[8];
    __shared__ float mt[4], lt[4];
    __shared__ float vpart[4][4][64];

    int bh   = blockIdx.x & 127;
    int cidx = blockIdx.x >> 7;
    int b = bh >> 4, h = bh & 15;
    int tid = threadIdx.x;
    int pos = pos_l[b];
    int slen = pos + T;
    int chunk = (slen + 3) >> 2;
    int s0 = cidx * chunk;
    int s1 = min(slen, s0 + chunk);
    int len = s1 - s0;
    int gbase = (bh * 4 + cidx) * 4;

    if (len <= 0) {
        po[(size_t)gbase * 64 + tid] = 0.f;
        if (tid < 4) { gm[gbase + tid] = -1e30f; gl[gbase + tid] = 0.f; }
        return;
    }

    {
        int t = tid >> 6, d = tid & 63;
        qs[t][d] = q[((size_t)(b * T + t) * E) + h * D + d];
    }
    __syncthreads();

    const float scale = 0.125f;
    for (int i = tid; i < len; i += 256) {
        int s = s0 + i;
        size_t off = ((size_t)b * L + s) * E + h * D;
        bool old = (s < pos);
        const float4* kr = (const float4*)((old ? kin : kout) + off);
        float d0 = 0.f, d1 = 0.f, d2 = 0.f, d3 = 0.f;
        #pragma unroll
        for (int i4 = 0; i4 < 16; i4++) {
            float4 kv = kr[i4];
            if (old) {
                kv.x = isnan(kv.x) ? 0.f : kv.x;
                kv.y = isnan(kv.y) ? 0.f : kv.y;
                kv.z = isnan(kv.z) ? 0.f : kv.z;
                kv.w = isnan(kv.w) ? 0.f : kv.w;
            }
            int d = i4 * 4;
            d0 += qs[0][d]*kv.x + qs[0][d+1]*kv.y + qs[0][d+2]*kv.z + qs[0][d+3]*kv.w;
            d1 += qs[1][d]*kv.x + qs[1][d+1]*kv.y + qs[1][d+2]*kv.z + qs[1][d+3]*kv.w;
            d2 += qs[2][d]*kv.x + qs[2][d+1]*kv.y + qs[2][d+2]*kv.z + qs[2][d+3]*kv.w;
            d3 += qs[3][d]*kv.x + qs[3][d+1]*kv.y + qs[3][d+2]*kv.z + qs[3][d+3]*kv.w;
        }
        sc[0][i] = (s <= pos + 0) ? d0 * scale : -1e30f;
        sc[1][i] = (s <= pos + 1) ? d1 * scale : -1e30f;
        sc[2][i] = (s <= pos + 2) ? d2 * scale : -1e30f;
        sc[3][i] = (s <= pos + 3) ? d3 * scale : -1e30f;
    }
    __syncthreads();

    #pragma unroll
    for (int t = 0; t < 4; t++) {
        float m = -1e30f;
        for (int i = tid; i < len; i += 256) m = fmaxf(m, sc[t][i]);
        #pragma unroll
        for (int o = 16; o > 0; o >>= 1) m = fmaxf(m, __shfl_xor_sync(0xffffffffu, m, o));
        if ((tid & 31) == 0) red[tid >> 5] = m;
        __syncthreads();
        m = fmaxf(fmaxf(fmaxf(red[0], red[1]), fmaxf(red[2], red[3])),
                  fmaxf(fmaxf(red[4], red[5]), fmaxf(red[6], red[7])));
        float ssum = 0.f;
        for (int i = tid; i < len; i += 256) {
            float e = __expf(sc[t][i] - m);
            sc[t][i] = e;
            ssum += e;
        }
        #pragma unroll
        for (int o = 16; o > 0; o >>= 1) ssum += __shfl_xor_sync(0xffffffffu, ssum, o);
        __syncthreads();
        if ((tid & 31) == 0) red[tid >> 5] = ssum;
        __syncthreads();
        if (tid == 0) {
            mt[t] = m;
            lt[t] = red[0]+red[1]+red[2]+red[3]+red[4]+red[5]+red[6]+red[7];
        }
        __syncthreads();
    }

    {
        int sg = tid >> 6, d = tid & 63;
        int q4 = (len + 3) >> 2;
        int i0 = sg * q4;
        int i1 = min(len, i0 + q4);
        float a0 = 0.f, a1 = 0.f, a2 = 0.f, a3 = 0.f;
        for (int i = i0; i < i1; i++) {
            int s = s0 + i;
            bool old = (s < pos);
            float v0 = (old ? vin : vout)[((size_t)b * L + s) * E + h * D + d];
            if (old) v0 = isnan(v0) ? 0.f : v0;
            a0 += sc[0][i] * v0;
            a1 += sc[1][i] * v0;
            a2 += sc[2][i] * v0;
            a3 += sc[3][i] * v0;
        }
        vpart[sg][0][d] = a0;
        vpart[sg][1][d] = a1;
        vpart[sg][2][d] = a2;
        vpart[sg][3][d] = a3;
    }
    __syncthreads();
    {
        int t = tid >> 6, d = tid & 63;
        float sum = vpart[0][t][d] + vpart[1][t][d] + vpart[2][t][d] + vpart[3][t][d];
        po[((size_t)(gbase + t)) * 64 + d] = sum;
        if (tid < 4) { gm[gbase + tid] = mt[tid]; gl[gbase + tid] = lt[tid]; }
    }
}

// -------- Attention combine --------
__global__ void attn_comb_kernel(const float* __restrict__ po,
                                 const float* __restrict__ gm,
                                 const float* __restrict__ gl,
                                 float* __restrict__ out)
{
    int bh = blockIdx.x;
    int b = bh >> 4, h = bh & 15;
    int tid = threadIdx.x;
    int t = tid >> 6, d = tid & 63;

    float m0 = gm[(bh * 4 + 0) * 4 + t];
    float m1 = gm[(bh * 4 + 1) * 4 + t];
    float m2 = gm[(bh * 4 + 2) * 4 + t];
    float m3 = gm[(bh * 4 + 3) * 4 + t];
    float M = fmaxf(fmaxf(m0, m1), fmaxf(m2, m3));
    float w0 = __expf(m0 - M), w1 = __expf(m1 - M);
    float w2 = __expf(m2 - M), w3 = __expf(m3 - M);
    float l = w0 * gl[(bh * 4 + 0) * 4 + t] + w1 * gl[(bh * 4 + 1) * 4 + t]
            + w2 * gl[(bh * 4 + 2) * 4 + t] + w3 * gl[(bh * 4 + 3) * 4 + t];
    float o = w0 * po[((size_t)(bh * 4 + 0) * 4 + t) * 64 + d]
            + w1 * po[((size_t)(bh * 4 + 1) * 4 + t) * 64 + d]
            + w2 * po[((size_t)(bh * 4 + 2) * 4 + t) * 64 + d]
            + w3 * po[((size_t)(bh * 4 + 3) * 4 + t) * 64 + d];
    out[((size_t)(b * T + t) * E) + h * D + d] = o / l;
}

extern "C" void kernel_launch(void* const* d_in, const int* in_sizes, int n_in,
                              void* d_out, int out_size)
{
    const float* seq       = (const float*)d_in[0];
    const float* bos       = (const float*)d_in[1];
    const float* caches    = (const float*)d_in[2];
    const int*   positions = (const int*)  d_in[3];
    const float* in_w      = (const float*)d_in[4];
    const float* ip_w      = (const float*)d_in[5];
    const float* op_w      = (const float*)d_in[6];
    const float* n1w       = (const float*)d_in[7];
    const float* n1b       = (const float*)d_in[8];
    const float* n2w       = (const float*)d_in[9];
    const float* n2b       = (const float*)d_in[10];
    const float* l1_w      = (const float*)d_in[11];
    const float* l2_w      = (const float*)d_in[12];
    const float* on_w      = (const float*)d_in[13];
    const float* on_b      = (const float*)d_in[14];
    const float* eos_w     = (const float*)d_in[15];
    const float* eos_b     = (const float*)d_in[16];

    float* out = (float*)d_out;
    const size_t cache_elems = (size_t)NL * 2 * B * L * E;
    float* out_x     = out;
    float* out_eos   = out + (size_t)NTOK * E;
    float* out_cache = out_eos + NTOK;
    float* out_pos   = out_cache + cache_elems;

    float *px, *pxn, *pq, *pattn, *ppart, *ppart2, *pseq, *ppo, *pm, *pl;
    cudaGetSymbolAddress((void**)&px,     g_x);
    cudaGetSymbolAddress((void**)&pxn,    g_xn);
    cudaGetSymbolAddress((void**)&pq,     g_q);
    cudaGetSymbolAddress((void**)&pattn,  g_attn);
    cudaGetSymbolAddress((void**)&ppart,  g_part);
    cudaGetSymbolAddress((void**)&ppart2, g_part2);
    cudaGetSymbolAddress((void**)&pseq,   g_seq);
    cudaGetSymbolAddress((void**)&ppo,    g_po);
    cudaGetSymbolAddress((void**)&pm,     g_m);
    cudaGetSymbolAddress((void**)&pl,     g_l);

    // ---- fork FIRST: small persistent copy grid co-resides with the chain ----
    cudaStream_t cs;
    cudaStreamCreateWithFlags(&cs, cudaStreamNonBlocking);
    cudaEvent_t evFork, evJoin;
    cudaEventCreateWithFlags(&evFork, cudaEventDisableTiming);
    cudaEventCreateWithFlags(&evJoin, cudaEventDisableTiming);

    cudaEventRecord(evFork, 0);
    cudaStreamWaitEvent(cs, evFork, 0);
    cache_copy_kernel<<<296, 256, 0, cs>>>((const float4*)caches,
                                           (float4*)out_cache, positions);
    cudaEventRecord(evJoin, cs);

    // ---- compute chain (independent of bulk copy) ----
    prep_pos_kernel<<<5, 256>>>(seq, bos, positions, pseq, out_pos);
    gemv64_kernel<0,1><<<E / 64, 256>>>(pseq, in_w, px, nullptr, INDIM, E);
    ln_kernel<<<NTOK, 256>>>(px, n1w, n1b, pxn);

    for (int i = 0; i < NL; i++) {
        const float* ipw = ip_w + (size_t)i * 3 * E * E;
        const float* opw = op_w + (size_t)i * E * E;
        const float* l1  = l1_w + (size_t)i * FF * E;
        const float* l2  = l2_w + (size_t)i * E * FF;
        float* kcache = out_cache + ((size_t)i * 2 + 0) * B * L * E;
        float* vcache = out_cache + ((size_t)i * 2 + 1) * B * L * E;
        const float* kcin = caches + ((size_t)i * 2 + 0) * B * L * E;
        const float* vcin = caches + ((size_t)i * 2 + 1) * B * L * E;
        const int* posl = positions + i * B;

        // qkv: K=1024, N=3072, split-K=2 -> 96 blocks
        gemv64_kernel<0,2><<<dim3(3 * E / 64, 2), 256>>>(pxn, ipw, nullptr, ppart2, E, 3 * E);
        reduce_rope_kernel<<<192, 256>>>(ppart2, posl, pq, kcache, vcache);

        attn_part_kernel<<<512, 256>>>(pq, kcin, vcin, kcache, vcache, posl, ppo, pm, pl);
        attn_comb_kernel<<<B * H, 256>>>(ppo, pm, pl, pattn);

        // op: K=1024, N=1024, split-K=8 -> 128 blocks
        gemv64_kernel<0,8><<<dim3(E / 64, 8), 256>>>(pattn, opw, nullptr, ppart2, E, E);
        reduce_ln_kernel<<<NTOK, 256>>>(ppart2, px, n2w + (size_t)i * E, n2b + (size_t)i * E, pxn);

        // l1: K=1024, N=4096, split-K=2 -> 128 blocks, partials (no gelu yet)
        gemv64_kernel<0,2><<<dim3(FF / 64, 2), 256>>>(pxn, l1, nullptr, ppart, E, FF);

        // l2: K=4096, N=1024, split-K=8, gelu fused on X load -> 128 blocks
        gemv64_kernel<1,8><<<dim3(E / 64, 8), 256>>>(ppart, l2, nullptr, ppart2, FF, E);

        if (i + 1 < NL) {
            reduce_ln_kernel<<<NTOK, 256>>>(ppart2, px,
                                            n1w + (size_t)(i + 1) * E,
                                            n1b + (size_t)(i + 1) * E, pxn);
        } else {
            reduce_ln_eos_kernel<<<NTOK, 256>>>(ppart2, px, on_w, on_b,
                                                eos_w, eos_b, out_x, out_eos);
        }
    }

    cudaStreamWaitEvent(0, evJoin, 0);
}

// round 9
// speedup vs baseline: 1.1097x; 1.1097x over previous
#include <cuda_runtime.h>
#include <math.h>

#define NL 6
#define B  8
#define T  4
#define L  2048
#define H  16
#define D  64
#define E  1024
#define FF 4096
#define INDIM 32
#define NTOK 32

#define CACHE_F4 50331648LL            // NL*2*B*L*E/4

// -------- scratch (device globals) --------
__device__ float g_x    [NTOK * E];
__device__ float g_xn   [NTOK * E];
__device__ float g_attn [NTOK * E];
__device__ float g_part [262144];      // l1 partials (2 x 32 x 4096)
__device__ float g_part2[393216];      // qkv (4x32x3072) / op,l2 (8x32x1024)
__device__ float g_po   [B * H * 4 * T * D];
__device__ float g_m    [B * H * 4 * T];
__device__ float g_l    [B * H * 4 * T];

// -------- f32x2 helpers --------
__device__ __forceinline__ unsigned long long pk2(float lo, float hi) {
    unsigned long long r;
    asm("mov.b64 %0, {%1, %2};" : "=l"(r) : "f"(lo), "f"(hi));
    return r;
}
__device__ __forceinline__ void fma2(unsigned long long& d,
                                     unsigned long long a,
                                     unsigned long long b) {
    asm("fma.rn.f32x2 %0, %1, %2, %3;" : "=l"(d) : "l"(a), "l"(b), "l"(d));
}
__device__ __forceinline__ float2 upk(unsigned long long v) {
    float2 f;
    asm("mov.b64 {%0, %1}, %2;" : "=f"(f.x), "=f"(f.y) : "l"(v));
    return f;
}
__device__ __forceinline__ float gelu1(float v) {
    return 0.5f * v * (1.0f + erff(v * 0.70710678118654752f));
}

// -------- bulk cache copy: big grid, serial (known ~240us) --------
__global__ void cache_copy_kernel(const float4* __restrict__ in,
                                  float4* __restrict__ out,
                                  const int* __restrict__ allpos)
{
    long long i = (long long)blockIdx.x * 256 + threadIdx.x;
    if (i >= CACHE_F4) return;
    unsigned slot = ((unsigned)(i >> 8)) & 2047u;
    unsigned b    = ((unsigned)(i >> 19)) & 7u;
    unsigned l    = ((unsigned)(i >> 22)) >> 1;
    int p = allpos[l * 8 + b];
    if ((unsigned)((int)slot - p) < (unsigned)T) return;   // new slot: attn scatter owns
    float4 v = in[i];
    v.x = isnan(v.x) ? 0.0f : v.x;
    v.y = isnan(v.y) ? 0.0f : v.y;
    v.z = isnan(v.z) ? 0.0f : v.z;
    v.w = isnan(v.w) ? 0.0f : v.w;
    out[i] = v;
}

// -------- embed: x = clean(seq) @ in_w^T; also out_pos --------
__global__ void embed_kernel(const float* __restrict__ seq,
                             const float* __restrict__ bos,
                             const int* __restrict__ positions,
                             const float* __restrict__ in_w,
                             float* __restrict__ x,
                             float* __restrict__ out_pos)
{
    __shared__ float srow[32];
    int bid = blockIdx.x;   // 128
    int tid = threadIdx.x;
    int tok = bid >> 2;
    if (tid < 32) {
        float v = seq[tok * INDIM + tid];
        srow[tid] = isnan(v) ? bos[tid] : v;
    }
    __syncthreads();
    int col = ((bid & 3) << 8) + tid;
    const float4* wr = (const float4*)(in_w + (size_t)col * INDIM);
    float acc = 0.f;
    #pragma unroll
    for (int k4 = 0; k4 < 8; k4++) {
        float4 w = wr[k4];
        acc += srow[k4*4]*w.x + srow[k4*4+1]*w.y + srow[k4*4+2]*w.z + srow[k4*4+3]*w.w;
    }
    x[(size_t)tok * E + col] = acc;
    if (bid == 127 && tid < NL * B)
        out_pos[tid] = (float)(positions[tid] + T);
}

// ======== GEMM: partials[ks][32,N] = X[32,Kc] @ W[N,Kc]^T ========
// 64-wide k-chunks, 2-deep register prefetch, f32x2 compute.
// GELUX=1: X = l1 split-K partial pair (rows r, r+32, stride K); gelu(p0+p1).
template<int GELUX>
__global__ void gemv64_kernel(const float* __restrict__ X,
                              const float* __restrict__ W,
                              float* __restrict__ part,
                              int K, int N)
{
    __shared__ alignas(16) unsigned long long XsP[32][33];   // [k2][row]
    __shared__ alignas(16) float Ws[64][68];

    const int t    = threadIdx.x;
    const int lane = t & 31;
    const int c0   = (t >> 5) * 8;
    const int n0   = blockIdx.x * 64;
    const int Kc   = K / gridDim.y;
    const int kbase = blockIdx.y * Kc;
    const int nch  = Kc >> 6;

    const int xrow = t >> 3, xk = (t & 7) * 8, x4 = (t & 7) * 4;
    const int wrow = t >> 2, wk = (t & 3) * 16;

    const float4* xg  = (const float4*)(X + (size_t)xrow * K + kbase + xk);
    const float4* x2g = (const float4*)(X + (size_t)(32 + xrow) * K + kbase + xk);
    const float4* wg  = (const float4*)(W + (size_t)(n0 + wrow) * K + kbase + wk);

    float4 xa0 = xg[0], xa1 = xg[1], xa20, xa21;
    float4 wa0 = wg[0], wa1 = wg[1], wa2 = wg[2], wa3 = wg[3];
    float4 xb0, xb1, xb20, xb21, wb0, wb1, wb2, wb3;
    if (GELUX) { xa20 = x2g[0]; xa21 = x2g[1]; }
    if (nch > 1) {
        xb0 = xg[16]; xb1 = xg[17];
        wb0 = wg[16]; wb1 = wg[17]; wb2 = wg[18]; wb3 = wg[19];
        if (GELUX) { xb20 = x2g[16]; xb21 = x2g[17]; }
    }

    unsigned long long acc[8];
    #pragma unroll
    for (int c = 0; c < 8; c++) acc[c] = 0ULL;

    for (int ch = 0; ch < nch; ch++) {
        float4 xs0, xs1, xs20, xs21, v0, v1, v2, v3;
        if ((ch & 1) == 0) {
            xs0 = xa0; xs1 = xa1; v0 = wa0; v1 = wa1; v2 = wa2; v3 = wa3;
            if (GELUX) { xs20 = xa20; xs21 = xa21; }
        } else {
            xs0 = xb0; xs1 = xb1; v0 = wb0; v1 = wb1; v2 = wb2; v3 = wb3;
            if (GELUX) { xs20 = xb20; xs21 = xb21; }
        }
        if (GELUX) {
            xs0.x = gelu1(xs0.x + xs20.x); xs0.y = gelu1(xs0.y + xs20.y);
            xs0.z = gelu1(xs0.z + xs20.z); xs0.w = gelu1(xs0.w + xs20.w);
            xs1.x = gelu1(xs1.x + xs21.x); xs1.y = gelu1(xs1.y + xs21.y);
            xs1.z = gelu1(xs1.z + xs21.z); xs1.w = gelu1(xs1.w + xs21.w);
        }
        XsP[x4    ][xrow] = pk2(xs0.x, xs0.y);
        XsP[x4 + 1][xrow] = pk2(xs0.z, xs0.w);
        XsP[x4 + 2][xrow] = pk2(xs1.x, xs1.y);
        XsP[x4 + 3][xrow] = pk2(xs1.z, xs1.w);
        *(float4*)&Ws[wrow][wk]      = v0;
        *(float4*)&Ws[wrow][wk + 4]  = v1;
        *(float4*)&Ws[wrow][wk + 8]  = v2;
        *(float4*)&Ws[wrow][wk + 12] = v3;
        __syncthreads();

        if (ch + 2 < nch) {
            int off = (ch + 2) * 16;
            if ((ch & 1) == 0) {
                xa0 = xg[off]; xa1 = xg[off + 1];
                wa0 = wg[off]; wa1 = wg[off + 1]; wa2 = wg[off + 2]; wa3 = wg[off + 3];
                if (GELUX) { xa20 = x2g[off]; xa21 = x2g[off + 1]; }
            } else {
                xb0 = xg[off]; xb1 = xg[off + 1];
                wb0 = wg[off]; wb1 = wg[off + 1]; wb2 = wg[off + 2]; wb3 = wg[off + 3];
                if (GELUX) { xb20 = x2g[off]; xb21 = x2g[off + 1]; }
            }
        }

        #pragma unroll
        for (int k2 = 0; k2 < 32; k2 += 2) {
            unsigned long long x0 = XsP[k2][lane];
            unsigned long long x1 = XsP[k2 + 1][lane];
            #pragma unroll
            for (int c = 0; c < 8; c++) {
                longlong2 w = *(const longlong2*)&Ws[c0 + c][k2 * 2];
                fma2(acc[c], x0, (unsigned long long)w.x);
                fma2(acc[c], x1, (unsigned long long)w.y);
            }
        }
        __syncthreads();
    }

    float* pp = part + ((size_t)blockIdx.y * 32 + lane) * N + n0 + c0;
    #pragma unroll
    for (int c = 0; c < 8; c++) {
        float2 p = upk(acc[c]);
        pp[c] = p.x + p.y;
    }
}

// -------- LayerNorm (layer-0 entry) --------
__global__ void ln_kernel(const float* __restrict__ X,
                          const float* __restrict__ w,
                          const float* __restrict__ b,
                          float* __restrict__ Y)
{
    int tok = blockIdx.x;
    int tid = threadIdx.x;
    const float* x = X + (size_t)tok * E;
    float v[4];
    #pragma unroll
    for (int j = 0; j < 4; j++) v[j] = x[tid + 256 * j];
    float s = v[0] + v[1] + v[2] + v[3];
    #pragma unroll
    for (int o = 16; o > 0; o >>= 1) s += __shfl_xor_sync(0xffffffffu, s, o);
    __shared__ float ws[8];
    if ((tid & 31) == 0) ws[tid >> 5] = s;
    __syncthreads();
    float mean = (ws[0]+ws[1]+ws[2]+ws[3]+ws[4]+ws[5]+ws[6]+ws[7]) * (1.0f / E);
    float s2 = 0.f;
    #pragma unroll
    for (int j = 0; j < 4; j++) { float d = v[j] - mean; s2 += d * d; }
    #pragma unroll
    for (int o = 16; o > 0; o >>= 1) s2 += __shfl_xor_sync(0xffffffffu, s2, o);
    __syncthreads();
    if ((tid & 31) == 0) ws[tid >> 5] = s2;
    __syncthreads();
    float var = (ws[0]+ws[1]+ws[2]+ws[3]+ws[4]+ws[5]+ws[6]+ws[7]) * (1.0f / E);
    float r = rsqrtf(var + 1e-5f);
    #pragma unroll
    for (int j = 0; j < 4; j++) {
        int idx = tid + 256 * j;
        Y[(size_t)tok * E + idx] = (v[j] - mean) * r * w[idx] + b[idx];
    }
}

// -------- fused: x += sum(8 partials); xn = LN(x) --------
__global__ void reduce_ln_kernel(const float* __restrict__ part,
                                 float* __restrict__ x,
                                 const float* __restrict__ w,
                                 const float* __restrict__ b,
                                 float* __restrict__ xn)
{
    int tok = blockIdx.x;
    int tid = threadIdx.x;
    float v[4];
    #pragma unroll
    for (int j = 0; j < 4; j++) {
        int idx = tid + 256 * j;
        float p = 0.f;
        #pragma unroll
        for (int k = 0; k < 8; k++) p += part[((size_t)(k * 32 + tok)) * E + idx];
        float xv = x[(size_t)tok * E + idx] + p;
        x[(size_t)tok * E + idx] = xv;
        v[j] = xv;
    }
    float s = v[0] + v[1] + v[2] + v[3];
    #pragma unroll
    for (int o = 16; o > 0; o >>= 1) s += __shfl_xor_sync(0xffffffffu, s, o);
    __shared__ float ws[8];
    if ((tid & 31) == 0) ws[tid >> 5] = s;
    __syncthreads();
    float mean = (ws[0]+ws[1]+ws[2]+ws[3]+ws[4]+ws[5]+ws[6]+ws[7]) * (1.0f / E);
    float s2 = 0.f;
    #pragma unroll
    for (int j = 0; j < 4; j++) { float d = v[j] - mean; s2 += d * d; }
    #pragma unroll
    for (int o = 16; o > 0; o >>= 1) s2 += __shfl_xor_sync(0xffffffffu, s2, o);
    __syncthreads();
    if ((tid & 31) == 0) ws[tid >> 5] = s2;
    __syncthreads();
    float var = (ws[0]+ws[1]+ws[2]+ws[3]+ws[4]+ws[5]+ws[6]+ws[7]) * (1.0f / E);
    float r = rsqrtf(var + 1e-5f);
    #pragma unroll
    for (int j = 0; j < 4; j++) {
        int idx = tid + 256 * j;
        xn[(size_t)tok * E + idx] = (v[j] - mean) * r * w[idx] + b[idx];
    }
}

// -------- fused: x += partials; out_x = LN(x); eos dot --------
__global__ void reduce_ln_eos_kernel(const float* __restrict__ part,
                                     float* __restrict__ x,
                                     const float* __restrict__ w,
                                     const float* __restrict__ b,
                                     const float* __restrict__ ew,
                                     const float* __restrict__ eb,
                                     float* __restrict__ Y,
                                     float* __restrict__ out_eos)
{
    int tok = blockIdx.x;
    int tid = threadIdx.x;
    float v[4];
    #pragma unroll
    for (int j = 0; j < 4; j++) {
        int idx = tid + 256 * j;
        float p = 0.f;
        #pragma unroll
        for (int k = 0; k < 8; k++) p += part[((size_t)(k * 32 + tok)) * E + idx];
        v[j] = x[(size_t)tok * E + idx] + p;
    }
    float s = v[0] + v[1] + v[2] + v[3];
    #pragma unroll
    for (int o = 16; o > 0; o >>= 1) s += __shfl_xor_sync(0xffffffffu, s, o);
    __shared__ float ws[8];
    if ((tid & 31) == 0) ws[tid >> 5] = s;
    __syncthreads();
    float mean = (ws[0]+ws[1]+ws[2]+ws[3]+ws[4]+ws[5]+ws[6]+ws[7]) * (1.0f / E);
    float s2 = 0.f;
    #pragma unroll
    for (int j = 0; j < 4; j++) { float d = v[j] - mean; s2 += d * d; }
    #pragma unroll
    for (int o = 16; o > 0; o >>= 1) s2 += __shfl_xor_sync(0xffffffffu, s2, o);
    __syncthreads();
    if ((tid & 31) == 0) ws[tid >> 5] = s2;
    __syncthreads();
    float var = (ws[0]+ws[1]+ws[2]+ws[3]+ws[4]+ws[5]+ws[6]+ws[7]) * (1.0f / E);
    float r = rsqrtf(var + 1e-5f);
    float ed = 0.f;
    #pragma unroll
    for (int j = 0; j < 4; j++) {
        int idx = tid + 256 * j;
        float y = (v[j] - mean) * r * w[idx] + b[idx];
        Y[(size_t)tok * E + idx] = y;
        ed += y * ew[idx];
    }
    #pragma unroll
    for (int o = 16; o > 0; o >>= 1) ed += __shfl_xor_sync(0xffffffffu, ed, o);
    __syncthreads();
    if ((tid & 31) == 0) ws[tid >> 5] = ed;
    __syncthreads();
    if (tid == 0)
        out_eos[tok] = ws[0]+ws[1]+ws[2]+ws[3]+ws[4]+ws[5]+ws[6]+ws[7] + eb[0];
}

// -------- Attention partial with fused qkv-reduce + RoPE + scatter --------
// part: 4 split-K partials of [32, 3072]. Old K/V from input cache (NaN-clean).
// New-slot K/V reduced+roped in-block (smem) and written once to output cache.
#define CMAX 260
__global__ void attn_part_kernel(const float* __restrict__ part,
                                 const float* __restrict__ kin,
                                 const float* __restrict__ vin,
                                 float* __restrict__ kcache,
                                 float* __restrict__ vcache,
                                 const int* __restrict__ pos_l,
                                 float* __restrict__ po,
                                 float* __restrict__ gm,
                                 float* __restrict__ gl)
{
    __shared__ float qs[4][64];
    __shared__ alignas(16) float kn[4][64];
    __shared__ alignas(16) float vn[4][64];
    __shared__ float sc[4][CMAX];
    __shared__ float red[8];
    __shared__ float mt[4], lt[4];
    __shared__ float vpart[4][4][64];

    int bh   = blockIdx.x & 127;
    int cidx = blockIdx.x >> 7;
    int b = bh >> 4, h = bh & 15;
    int tid = threadIdx.x;
    int pos = pos_l[b];
    int slen = pos + T;
    int chunk = (slen + 3) >> 2;
    int s0 = cidx * chunk;
    int s1 = min(slen, s0 + chunk);
    int len = s1 - s0;
    int gbase = (bh * 4 + cidx) * 4;

    if (len <= 0) {
        po[(size_t)gbase * 64 + tid] = 0.f;
        if (tid < 4) { gm[gbase + tid] = -1e30f; gl[gbase + tid] = 0.f; }
        return;
    }

    const float LOGC = logf(10000.0f) / 32.0f;

    // q reduce + rope (128 threads: 4 tokens x 32 pairs)
    if (tid < 128) {
        int t = tid >> 5, j = tid & 31;
        int tok = b * T + t;
        size_t base = (size_t)tok * 3072 + h * 64 + 2 * j;
        float p0 = part[base]                + part[base + 32 * 3072]
                 + part[base + 64 * 3072]    + part[base + 96 * 3072];
        float p1 = part[base + 1]            + part[base + 1 + 32 * 3072]
                 + part[base + 1 + 64 * 3072]+ part[base + 1 + 96 * 3072];
        float freq = __expf(-(float)j * LOGC);
        float sn, cs;
        sincosf((float)(pos + t) * freq, &sn, &cs);
        qs[t][2 * j]     = p0 * cs - p1 * sn;
        qs[t][2 * j + 1] = p0 * sn + p1 * cs;
    } else {
        // new-slot K reduce + rope (128 threads: 4 tokens x 32 pairs)
        int t = (tid - 128) >> 5, j = (tid - 128) & 31;
        int s = pos + t;
        if (s >= s0 && s < s1) {
            int tok = b * T + t;
            size_t base = (size_t)tok * 3072 + E + h * 64 + 2 * j;
            float p0 = part[base]                + part[base + 32 * 3072]
                     + part[base + 64 * 3072]    + part[base + 96 * 3072];
            float p1 = part[base + 1]            + part[base + 1 + 32 * 3072]
                     + part[base + 1 + 64 * 3072]+ part[base + 1 + 96 * 3072];
            float freq = __expf(-(float)j * LOGC);
            float sn, cs;
            sincosf((float)s * freq, &sn, &cs);
            float k0 = p0 * cs - p1 * sn;
            float k1 = p0 * sn + p1 * cs;
            kn[t][2 * j]     = k0;
            kn[t][2 * j + 1] = k1;
            int slot = s % L;
            size_t off = ((size_t)b * L + slot) * E + h * D + 2 * j;
            kcache[off]     = k0;
            kcache[off + 1] = k1;
        }
    }
    // new-slot V reduce (all 256 threads: 4 tokens x 64 d)
    {
        int t = tid >> 6, d = tid & 63;
        int s = pos + t;
        if (s >= s0 && s < s1) {
            int tok = b * T + t;
            size_t base = (size_t)tok * 3072 + 2 * E + h * 64 + d;
            float p = part[base]                + part[base + 32 * 3072]
                    + part[base + 64 * 3072]    + part[base + 96 * 3072];
            vn[t][d] = p;
            int slot = s % L;
            vcache[((size_t)b * L + slot) * E + h * D + d] = p;
        }
    }
    __syncthreads();

    const float scale = 0.125f;
    for (int i = tid; i < len; i += 256) {
        int s = s0 + i;
        bool old = (s < pos);
        const float4* kr = old
            ? (const float4*)(kin + ((size_t)b * L + s) * E + h * D)
            : (const float4*)&kn[s - pos][0];
        float d0 = 0.f, d1 = 0.f, d2 = 0.f, d3 = 0.f;
        #pragma unroll
        for (int i4 = 0; i4 < 16; i4++) {
            float4 kv = kr[i4];
            if (old) {
                kv.x = isnan(kv.x) ? 0.f : kv.x;
                kv.y = isnan(kv.y) ? 0.f : kv.y;
                kv.z = isnan(kv.z) ? 0.f : kv.z;
                kv.w = isnan(kv.w) ? 0.f : kv.w;
            }
            int d = i4 * 4;
            d0 += qs[0][d]*kv.x + qs[0][d+1]*kv.y + qs[0][d+2]*kv.z + qs[0][d+3]*kv.w;
            d1 += qs[1][d]*kv.x + qs[1][d+1]*kv.y + qs[1][d+2]*kv.z + qs[1][d+3]*kv.w;
            d2 += qs[2][d]*kv.x + qs[2][d+1]*kv.y + qs[2][d+2]*kv.z + qs[2][d+3]*kv.w;
            d3 += qs[3][d]*kv.x + qs[3][d+1]*kv.y + qs[3][d+2]*kv.z + qs[3][d+3]*kv.w;
        }
        sc[0][i] = (s <= pos + 0) ? d0 * scale : -1e30f;
        sc[1][i] = (s <= pos + 1) ? d1 * scale : -1e30f;
        sc[2][i] = (s <= pos + 2) ? d2 * scale : -1e30f;
        sc[3][i] = (s <= pos + 3) ? d3 * scale : -1e30f;
    }
    __syncthreads();

    #pragma unroll
    for (int t = 0; t < 4; t++) {
        float m = -1e30f;
        for (int i = tid; i < len; i += 256) m = fmaxf(m, sc[t][i]);
        #pragma unroll
        for (int o = 16; o > 0; o >>= 1) m = fmaxf(m, __shfl_xor_sync(0xffffffffu, m, o));
        if ((tid & 31) == 0) red[tid >> 5] = m;
        __syncthreads();
        m = fmaxf(fmaxf(fmaxf(red[0], red[1]), fmaxf(red[2], red[3])),
                  fmaxf(fmaxf(red[4], red[5]), fmaxf(red[6], red[7])));
        float ssum = 0.f;
        for (int i = tid; i < len; i += 256) {
            float e = __expf(sc[t][i] - m);
            sc[t][i] = e;
            ssum += e;
        }
        #pragma unroll
        for (int o = 16; o > 0; o >>= 1) ssum += __shfl_xor_sync(0xffffffffu, ssum, o);
        __syncthreads();
        if ((tid & 31) == 0) red[tid >> 5] = ssum;
        __syncthreads();
        if (tid == 0) {
            mt[t] = m;
            lt[t] = red[0]+red[1]+red[2]+red[3]+red[4]+red[5]+red[6]+red[7];
        }
        __syncthreads();
    }

    {
        int sg = tid >> 6, d = tid & 63;
        int q4 = (len + 3) >> 2;
        int i0 = sg * q4;
        int i1 = min(len, i0 + q4);
        float a0 = 0.f, a1 = 0.f, a2 = 0.f, a3 = 0.f;
        for (int i = i0; i < i1; i++) {
            int s = s0 + i;
            bool old = (s < pos);
            float v0;
            if (old) {
                v0 = vin[((size_t)b * L + s) * E + h * D + d];
                v0 = isnan(v0) ? 0.f : v0;
            } else {
                v0 = vn[s - pos][d];
            }
            a0 += sc[0][i] * v0;
            a1 += sc[1][i] * v0;
            a2 += sc[2][i] * v0;
            a3 += sc[3][i] * v0;
        }
        vpart[sg][0][d] = a0;
        vpart[sg][1][d] = a1;
        vpart[sg][2][d] = a2;
        vpart[sg][3][d] = a3;
    }
    __syncthreads();
    {
        int t = tid >> 6, d = tid & 63;
        float sum = vpart[0][t][d] + vpart[1][t][d] + vpart[2][t][d] + vpart[3][t][d];
        po[((size_t)(gbase + t)) * 64 + d] = sum;
        if (tid < 4) { gm[gbase + tid] = mt[tid]; gl[gbase + tid] = lt[tid]; }
    }
}

// -------- Attention combine --------
__global__ void attn_comb_kernel(const float* __restrict__ po,
                                 const float* __restrict__ gm,
                                 const float* __restrict__ gl,
                                 float* __restrict__ out)
{
    int bh = blockIdx.x;
    int b = bh >> 4, h = bh & 15;
    int tid = threadIdx.x;
    int t = tid >> 6, d = tid & 63;

    float m0 = gm[(bh * 4 + 0) * 4 + t];
    float m1 = gm[(bh * 4 + 1) * 4 + t];
    float m2 = gm[(bh * 4 + 2) * 4 + t];
    float m3 = gm[(bh * 4 + 3) * 4 + t];
    float M = fmaxf(fmaxf(m0, m1), fmaxf(m2, m3));
    float w0 = __expf(m0 - M), w1 = __expf(m1 - M);
    float w2 = __expf(m2 - M), w3 = __expf(m3 - M);
    float l = w0 * gl[(bh * 4 + 0) * 4 + t] + w1 * gl[(bh * 4 + 1) * 4 + t]
            + w2 * gl[(bh * 4 + 2) * 4 + t] + w3 * gl[(bh * 4 + 3) * 4 + t];
    float o = w0 * po[((size_t)(bh * 4 + 0) * 4 + t) * 64 + d]
            + w1 * po[((size_t)(bh * 4 + 1) * 4 + t) * 64 + d]
            + w2 * po[((size_t)(bh * 4 + 2) * 4 + t) * 64 + d]
            + w3 * po[((size_t)(bh * 4 + 3) * 4 + t) * 64 + d];
    out[((size_t)(b * T + t) * E) + h * D + d] = o / l;
}

extern "C" void kernel_launch(void* const* d_in, const int* in_sizes, int n_in,
                              void* d_out, int out_size)
{
    const float* seq       = (const float*)d_in[0];
    const float* bos       = (const float*)d_in[1];
    const float* caches    = (const float*)d_in[2];
    const int*   positions = (const int*)  d_in[3];
    const float* in_w      = (const float*)d_in[4];
    const float* ip_w      = (const float*)d_in[5];
    const float* op_w      = (const float*)d_in[6];
    const float* n1w       = (const float*)d_in[7];
    const float* n1b       = (const float*)d_in[8];
    const float* n2w       = (const float*)d_in[9];
    const float* n2b       = (const float*)d_in[10];
    const float* l1_w      = (const float*)d_in[11];
    const float* l2_w      = (const float*)d_in[12];
    const float* on_w      = (const float*)d_in[13];
    const float* on_b      = (const float*)d_in[14];
    const float* eos_w     = (const float*)d_in[15];
    const float* eos_b     = (const float*)d_in[16];

    float* out = (float*)d_out;
    const size_t cache_elems = (size_t)NL * 2 * B * L * E;
    float* out_x     = out;
    float* out_eos   = out + (size_t)NTOK * E;
    float* out_cache = out_eos + NTOK;
    float* out_pos   = out_cache + cache_elems;

    float *px, *pxn, *pattn, *ppart, *ppart2, *ppo, *pm, *pl;
    cudaGetSymbolAddress((void**)&px,     g_x);
    cudaGetSymbolAddress((void**)&pxn,    g_xn);
    cudaGetSymbolAddress((void**)&pattn,  g_attn);
    cudaGetSymbolAddress((void**)&ppart,  g_part);
    cudaGetSymbolAddress((void**)&ppart2, g_part2);
    cudaGetSymbolAddress((void**)&ppo,    g_po);
    cudaGetSymbolAddress((void**)&pm,     g_m);
    cudaGetSymbolAddress((void**)&pl,     g_l);

    // serial bulk copy first (big grid, near BW floor)
    cache_copy_kernel<<<(unsigned)((CACHE_F4 + 255) / 256), 256>>>(
        (const float4*)caches, (float4*)out_cache, positions);

    embed_kernel<<<128, 256>>>(seq, bos, positions, in_w, px, out_pos);
    ln_kernel<<<NTOK, 256>>>(px, n1w, n1b, pxn);

    for (int i = 0; i < NL; i++) {
        const float* ipw = ip_w + (size_t)i * 3 * E * E;
        const float* opw = op_w + (size_t)i * E * E;
        const float* l1  = l1_w + (size_t)i * FF * E;
        const float* l2  = l2_w + (size_t)i * E * FF;
        float* kcache = out_cache + ((size_t)i * 2 + 0) * B * L * E;
        float* vcache = out_cache + ((size_t)i * 2 + 1) * B * L * E;
        const float* kcin = caches + ((size_t)i * 2 + 0) * B * L * E;
        const float* vcin = caches + ((size_t)i * 2 + 1) * B * L * E;
        const int* posl = positions + i * B;

        // qkv: K=1024, N=3072, split-K=4 -> 192 blocks (Kc=256, 4 chunks)
        gemv64_kernel<0><<<dim3(3 * E / 64, 4), 256>>>(pxn, ipw, ppart2, E, 3 * E);

        // attention (fused qkv-reduce + rope + scatter)
        attn_part_kernel<<<512, 256>>>(ppart2, kcin, vcin, kcache, vcache, posl,
                                       ppo, pm, pl);
        attn_comb_kernel<<<B * H, 256>>>(ppo, pm, pl, pattn);

        // op: K=1024, N=1024, split-K=8 -> 128 blocks (Kc=128, 2 chunks)
        gemv64_kernel<0><<<dim3(E / 64, 8), 256>>>(pattn, opw, ppart2, E, E);
        reduce_ln_kernel<<<NTOK, 256>>>(ppart2, px, n2w + (size_t)i * E, n2b + (size_t)i * E, pxn);

        // l1: K=1024, N=4096, split-K=2 -> 128 blocks (Kc=512, 8 chunks)
        gemv64_kernel<0><<<dim3(FF / 64, 2), 256>>>(pxn, l1, ppart, E, FF);

        // l2: K=4096, N=1024, split-K=8, gelu fused on X load -> 128 blocks
        gemv64_kernel<1><<<dim3(E / 64, 8), 256>>>(ppart, l2, ppart2, FF, E);

        if (i + 1 < NL) {
            reduce_ln_kernel<<<NTOK, 256>>>(ppart2, px,
                                            n1w + (size_t)(i + 1) * E,
                                            n1b + (size_t)(i + 1) * E, pxn);
        } else {
            reduce_ln_eos_kernel<<<NTOK, 256>>>(ppart2, px, on_w, on_b,
                                                eos_w, eos_b, out_x, out_eos);
        }
    }
}

// round 10
// speedup vs baseline: 1.1740x; 1.0579x over previous
#include <cuda_runtime.h>
#include <math.h>

#define NL 6
#define B  8
#define T  4
#define L  2048
#define H  16
#define D  64
#define E  1024
#define FF 4096
#define INDIM 32
#define NTOK 32

#define CACHE_F4 50331648LL            // NL*2*B*L*E/4

// -------- scratch (device globals) --------
__device__ float g_x    [NTOK * E];
__device__ float g_xn   [NTOK * E];
__device__ float g_q    [NTOK * E];
__device__ float g_attn [NTOK * E];
__device__ float g_part [524288];      // l1 partials (4 x 32 x 4096)
__device__ float g_part2[786432];      // qkv (8x32x3072) / op,l2 (16x32x1024)
__device__ float g_seq  [NTOK * INDIM];
__device__ float g_po   [B * H * 4 * T * D];
__device__ float g_m    [B * H * 4 * T];
__device__ float g_l    [B * H * 4 * T];

// -------- f32x2 helpers --------
__device__ __forceinline__ unsigned long long pk2(float lo, float hi) {
    unsigned long long r;
    asm("mov.b64 %0, {%1, %2};" : "=l"(r) : "f"(lo), "f"(hi));
    return r;
}
__device__ __forceinline__ void fma2(unsigned long long& d,
                                     unsigned long long a,
                                     unsigned long long b) {
    asm("fma.rn.f32x2 %0, %1, %2, %3;" : "=l"(d) : "l"(a), "l"(b), "l"(d));
}
__device__ __forceinline__ float2 upk(unsigned long long v) {
    float2 f;
    asm("mov.b64 {%0, %1}, %2;" : "=f"(f.x), "=f"(f.y) : "l"(v));
    return f;
}
__device__ __forceinline__ float gelu1(float v) {
    return 0.5f * v * (1.0f + erff(v * 0.70710678118654752f));
}

// -------- bulk cache copy: big grid, serial (~240us, near BW floor) --------
__global__ void cache_copy_kernel(const float4* __restrict__ in,
                                  float4* __restrict__ out,
                                  const int* __restrict__ allpos)
{
    long long i = (long long)blockIdx.x * 256 + threadIdx.x;
    if (i >= CACHE_F4) return;
    unsigned slot = ((unsigned)(i >> 8)) & 2047u;
    unsigned b    = ((unsigned)(i >> 19)) & 7u;
    unsigned l    = ((unsigned)(i >> 22)) >> 1;
    int p = allpos[l * 8 + b];
    if ((unsigned)((int)slot - p) < (unsigned)T) return;   // new slot: scatter owns
    float4 v = in[i];
    v.x = isnan(v.x) ? 0.0f : v.x;
    v.y = isnan(v.y) ? 0.0f : v.y;
    v.z = isnan(v.z) ? 0.0f : v.z;
    v.w = isnan(v.w) ? 0.0f : v.w;
    out[i] = v;
}

// -------- prep seq (NaN->bos) + new positions --------
__global__ void prep_pos_kernel(const float* __restrict__ seq,
                                const float* __restrict__ bos,
                                const int* __restrict__ positions,
                                float* __restrict__ out_seq,
                                float* __restrict__ out_pos)
{
    if (blockIdx.x < 4) {
        int i = blockIdx.x * 256 + threadIdx.x;
        float v = seq[i];
        out_seq[i] = isnan(v) ? bos[i & (INDIM - 1)] : v;
    } else {
        int i = threadIdx.x;
        if (i < NL * B) out_pos[i] = (float)(positions[i] + T);
    }
}

// ======== GEMM: Y/partials = X[32,K] @ W[N,K]^T, f32x2, 2-deep prefetch ====
// 32-wide k-chunks. GELUX: number of l1 partial buffers to sum+gelu on X load
// (0 = plain X). KSPLIT==1: direct store to Y.
template<int GELUX, int KSPLIT>
__global__ void gemv64_kernel(const float* __restrict__ X,
                              const float* __restrict__ W,
                              float* __restrict__ Y,
                              float* __restrict__ part,
                              int K, int N)
{
    __shared__ alignas(16) float Ws[64][36];
    __shared__ alignas(16) unsigned long long XsP[16][33];

    const int t    = threadIdx.x;
    const int lane = t & 31;
    const int c0   = (t >> 5) * 8;
    const int n0   = blockIdx.x * 64;
    const int Kc   = K / KSPLIT;
    const int kbase = blockIdx.y * Kc;
    const int nch  = Kc >> 5;

    const int xrow = t >> 3, xk = (t & 7) * 4;
    const int wrow = t >> 2, wk = (t & 3) * 8;

    const float4* xg  = (const float4*)(X + (size_t)xrow * K + kbase + xk);
    const float4* x2g = (const float4*)(X + (size_t)(32 + xrow) * K + kbase + xk);
    const float4* x3g = (const float4*)(X + (size_t)(64 + xrow) * K + kbase + xk);
    const float4* x4g = (const float4*)(X + (size_t)(96 + xrow) * K + kbase + xk);
    const float4* wg  = (const float4*)(W + (size_t)(n0 + wrow) * K + kbase + wk);

    float4 xa = xg[0], xa2, xa3, xa4, xb, xb2, xb3, xb4;
    float4 wa0 = wg[0], wa1 = wg[1], wb0, wb1;
    if (GELUX >= 2) xa2 = x2g[0];
    if (GELUX >= 4) { xa3 = x3g[0]; xa4 = x4g[0]; }
    if (nch > 1) {
        xb = xg[8]; wb0 = wg[8]; wb1 = wg[9];
        if (GELUX >= 2) xb2 = x2g[8];
        if (GELUX >= 4) { xb3 = x3g[8]; xb4 = x4g[8]; }
    }

    unsigned long long acc[8];
    #pragma unroll
    for (int c = 0; c < 8; c++) acc[c] = 0ULL;

    for (int ch = 0; ch < nch; ch++) {
        float4 xs, xs2, xs3, xs4, ws0, ws1;
        if ((ch & 1) == 0) {
            xs = xa; ws0 = wa0; ws1 = wa1;
            if (GELUX >= 2) xs2 = xa2;
            if (GELUX >= 4) { xs3 = xa3; xs4 = xa4; }
        } else {
            xs = xb; ws0 = wb0; ws1 = wb1;
            if (GELUX >= 2) xs2 = xb2;
            if (GELUX >= 4) { xs3 = xb3; xs4 = xb4; }
        }
        if (GELUX >= 2) {
            float sx = xs.x + xs2.x, sy = xs.y + xs2.y;
            float sz = xs.z + xs2.z, sw = xs.w + xs2.w;
            if (GELUX >= 4) {
                sx += xs3.x + xs4.x; sy += xs3.y + xs4.y;
                sz += xs3.z + xs4.z; sw += xs3.w + xs4.w;
            }
            xs.x = gelu1(sx); xs.y = gelu1(sy); xs.z = gelu1(sz); xs.w = gelu1(sw);
        }
        XsP[(xk >> 1)    ][xrow] = pk2(xs.x, xs.y);
        XsP[(xk >> 1) + 1][xrow] = pk2(xs.z, xs.w);
        *(float4*)&Ws[wrow][wk]     = ws0;
        *(float4*)&Ws[wrow][wk + 4] = ws1;
        __syncthreads();

        if (ch + 2 < nch) {
            int off = (ch + 2) * 8;
            if ((ch & 1) == 0) {
                xa = xg[off]; wa0 = wg[off]; wa1 = wg[off + 1];
                if (GELUX >= 2) xa2 = x2g[off];
                if (GELUX >= 4) { xa3 = x3g[off]; xa4 = x4g[off]; }
            } else {
                xb = xg[off]; wb0 = wg[off]; wb1 = wg[off + 1];
                if (GELUX >= 2) xb2 = x2g[off];
                if (GELUX >= 4) { xb3 = x3g[off]; xb4 = x4g[off]; }
            }
        }

        #pragma unroll
        for (int k2 = 0; k2 < 16; k2 += 2) {
            unsigned long long x0 = XsP[k2][lane];
            unsigned long long x1 = XsP[k2 + 1][lane];
            #pragma unroll
            for (int c = 0; c < 8; c++) {
                longlong2 w = *(const longlong2*)&Ws[c0 + c][k2 * 2];
                fma2(acc[c], x0, (unsigned long long)w.x);
                fma2(acc[c], x1, (unsigned long long)w.y);
            }
        }
        __syncthreads();
    }

    if (KSPLIT == 1) {
        #pragma unroll
        for (int c = 0; c < 8; c++) {
            float2 p = upk(acc[c]);
            Y[(size_t)lane * N + n0 + c0 + c] = p.x + p.y;
        }
    } else {
        float* pp = part + ((size_t)blockIdx.y * 32 + lane) * N + n0 + c0;
        #pragma unroll
        for (int c = 0; c < 8; c++) {
            float2 p = upk(acc[c]);
            pp[c] = p.x + p.y;
        }
    }
}

// -------- fused qkv split-K(8) reduce + RoPE + cache scatter --------
__global__ void reduce_rope_kernel(const float* __restrict__ part,
                                   const int* __restrict__ pos_l,
                                   float* __restrict__ qout,
                                   float* __restrict__ kcache,
                                   float* __restrict__ vcache)
{
    int id = blockIdx.x * 256 + threadIdx.x;  // 49152 pairs
    int tok = id / 1536;
    int f   = (id - tok * 1536) * 2;
    float s0 = 0.f, s1 = 0.f;
    #pragma unroll
    for (int k = 0; k < 8; k++) {
        const float* p = part + ((size_t)(k * 32 + tok) * 3072) + f;
        s0 += p[0];
        s1 += p[1];
    }
    int b = tok >> 2, t = tok & 3;
    int pos = pos_l[b];
    if (f < E) {
        int j = (f & 63) >> 1;
        float freq = __expf(-(float)j * (logf(10000.0f) / 32.0f));
        float sn, cs;
        sincosf((float)(pos + t) * freq, &sn, &cs);
        qout[(size_t)tok * E + f]     = s0 * cs - s1 * sn;
        qout[(size_t)tok * E + f + 1] = s0 * sn + s1 * cs;
    } else if (f < 2 * E) {
        int fk = f - E;
        int j = (fk & 63) >> 1;
        float freq = __expf(-(float)j * (logf(10000.0f) / 32.0f));
        float sn, cs;
        sincosf((float)(pos + t) * freq, &sn, &cs);
        int slot = (pos + t) % L;
        size_t off = ((size_t)b * L + slot) * E + fk;
        kcache[off]     = s0 * cs - s1 * sn;
        kcache[off + 1] = s0 * sn + s1 * cs;
    } else {
        int fv = f - 2 * E;
        int slot = (pos + t) % L;
        size_t off = ((size_t)b * L + slot) * E + fv;
        vcache[off]     = s0;
        vcache[off + 1] = s1;
    }
}

// -------- LayerNorm (layer-0 entry) --------
__global__ void ln_kernel(const float* __restrict__ X,
                          const float* __restrict__ w,
                          const float* __restrict__ b,
                          float* __restrict__ Y)
{
    int tok = blockIdx.x;
    int tid = threadIdx.x;
    const float* x = X + (size_t)tok * E;
    float v[4];
    #pragma unroll
    for (int j = 0; j < 4; j++) v[j] = x[tid + 256 * j];
    float s = v[0] + v[1] + v[2] + v[3];
    #pragma unroll
    for (int o = 16; o > 0; o >>= 1) s += __shfl_xor_sync(0xffffffffu, s, o);
    __shared__ float ws[8];
    if ((tid & 31) == 0) ws[tid >> 5] = s;
    __syncthreads();
    float mean = (ws[0]+ws[1]+ws[2]+ws[3]+ws[4]+ws[5]+ws[6]+ws[7]) * (1.0f / E);
    float s2 = 0.f;
    #pragma unroll
    for (int j = 0; j < 4; j++) { float d = v[j] - mean; s2 += d * d; }
    #pragma unroll
    for (int o = 16; o > 0; o >>= 1) s2 += __shfl_xor_sync(0xffffffffu, s2, o);
    __syncthreads();
    if ((tid & 31) == 0) ws[tid >> 5] = s2;
    __syncthreads();
    float var = (ws[0]+ws[1]+ws[2]+ws[3]+ws[4]+ws[5]+ws[6]+ws[7]) * (1.0f / E);
    float r = rsqrtf(var + 1e-5f);
    #pragma unroll
    for (int j = 0; j < 4; j++) {
        int idx = tid + 256 * j;
        Y[(size_t)tok * E + idx] = (v[j] - mean) * r * w[idx] + b[idx];
    }
}

// -------- fused: x += sum(KS partials); xn = LN(x) --------
template<int KS>
__global__ void reduce_ln_kernel(const float* __restrict__ part,
                                 float* __restrict__ x,
                                 const float* __restrict__ w,
                                 const float* __restrict__ b,
                                 float* __restrict__ xn)
{
    int tok = blockIdx.x;
    int tid = threadIdx.x;
    float v[4];
    #pragma unroll
    for (int j = 0; j < 4; j++) {
        int idx = tid + 256 * j;
        float p = 0.f;
        #pragma unroll
        for (int k = 0; k < KS; k++) p += part[((size_t)(k * 32 + tok)) * E + idx];
        float xv = x[(size_t)tok * E + idx] + p;
        x[(size_t)tok * E + idx] = xv;
        v[j] = xv;
    }
    float s = v[0] + v[1] + v[2] + v[3];
    #pragma unroll
    for (int o = 16; o > 0; o >>= 1) s += __shfl_xor_sync(0xffffffffu, s, o);
    __shared__ float ws[8];
    if ((tid & 31) == 0) ws[tid >> 5] = s;
    __syncthreads();
    float mean = (ws[0]+ws[1]+ws[2]+ws[3]+ws[4]+ws[5]+ws[6]+ws[7]) * (1.0f / E);
    float s2 = 0.f;
    #pragma unroll
    for (int j = 0; j < 4; j++) { float d = v[j] - mean; s2 += d * d; }
    #pragma unroll
    for (int o = 16; o > 0; o >>= 1) s2 += __shfl_xor_sync(0xffffffffu, s2, o);
    __syncthreads();
    if ((tid & 31) == 0) ws[tid >> 5] = s2;
    __syncthreads();
    float var = (ws[0]+ws[1]+ws[2]+ws[3]+ws[4]+ws[5]+ws[6]+ws[7]) * (1.0f / E);
    float r = rsqrtf(var + 1e-5f);
    #pragma unroll
    for (int j = 0; j < 4; j++) {
        int idx = tid + 256 * j;
        xn[(size_t)tok * E + idx] = (v[j] - mean) * r * w[idx] + b[idx];
    }
}

// -------- fused: x += sum(16 partials); out_x = LN(x); eos dot --------
__global__ void reduce_ln_eos_kernel(const float* __restrict__ part,
                                     float* __restrict__ x,
                                     const float* __restrict__ w,
                                     const float* __restrict__ b,
                                     const float* __restrict__ ew,
                                     const float* __restrict__ eb,
                                     float* __restrict__ Y,
                                     float* __restrict__ out_eos)
{
    int tok = blockIdx.x;
    int tid = threadIdx.x;
    float v[4];
    #pragma unroll
    for (int j = 0; j < 4; j++) {
        int idx = tid + 256 * j;
        float p = 0.f;
        #pragma unroll
        for (int k = 0; k < 16; k++) p += part[((size_t)(k * 32 + tok)) * E + idx];
        v[j] = x[(size_t)tok * E + idx] + p;
    }
    float s = v[0] + v[1] + v[2] + v[3];
    #pragma unroll
    for (int o = 16; o > 0; o >>= 1) s += __shfl_xor_sync(0xffffffffu, s, o);
    __shared__ float ws[8];
    if ((tid & 31) == 0) ws[tid >> 5] = s;
    __syncthreads();
    float mean = (ws[0]+ws[1]+ws[2]+ws[3]+ws[4]+ws[5]+ws[6]+ws[7]) * (1.0f / E);
    float s2 = 0.f;
    #pragma unroll
    for (int j = 0; j < 4; j++) { float d = v[j] - mean; s2 += d * d; }
    #pragma unroll
    for (int o = 16; o > 0; o >>= 1) s2 += __shfl_xor_sync(0xffffffffu, s2, o);
    __syncthreads();
    if ((tid & 31) == 0) ws[tid >> 5] = s2;
    __syncthreads();
    float var = (ws[0]+ws[1]+ws[2]+ws[3]+ws[4]+ws[5]+ws[6]+ws[7]) * (1.0f / E);
    float r = rsqrtf(var + 1e-5f);
    float ed = 0.f;
    #pragma unroll
    for (int j = 0; j < 4; j++) {
        int idx = tid + 256 * j;
        float y = (v[j] - mean) * r * w[idx] + b[idx];
        Y[(size_t)tok * E + idx] = y;
        ed += y * ew[idx];
    }
    #pragma unroll
    for (int o = 16; o > 0; o >>= 1) ed += __shfl_xor_sync(0xffffffffu, ed, o);
    __syncthreads();
    if ((tid & 31) == 0) ws[tid >> 5] = ed;
    __syncthreads();
    if (tid == 0)
        out_eos[tok] = ws[0]+ws[1]+ws[2]+ws[3]+ws[4]+ws[5]+ws[6]+ws[7] + eb[0];
}

// -------- Attention partial: grid 512, old K/V from input cache --------
#define CMAX 260
__global__ void attn_part_kernel(const float* __restrict__ q,
                                 const float* __restrict__ kin,
                                 const float* __restrict__ vin,
                                 const float* __restrict__ kout,
                                 const float* __restrict__ vout,
                                 const int* __restrict__ pos_l,
                                 float* __restrict__ po,
                                 float* __restrict__ gm,
                                 float* __restrict__ gl)
{
    __shared__ float qs[4][64];
    __shared__ float sc[4][CMAX];
    __shared__ float red[8];
    __shared__ float mt[4], lt[4];
    __shared__ float vpart[4][4][64];

    int bh   = blockIdx.x & 127;
    int cidx = blockIdx.x >> 7;
    int b = bh >> 4, h = bh & 15;
    int tid = threadIdx.x;
    int pos = pos_l[b];
    int slen = pos + T;
    int chunk = (slen + 3) >> 2;
    int s0 = cidx * chunk;
    int s1 = min(slen, s0 + chunk);
    int len = s1 - s0;
    int gbase = (bh * 4 + cidx) * 4;

    if (len <= 0) {
        po[(size_t)gbase * 64 + tid] = 0.f;
        if (tid < 4) { gm[gbase + tid] = -1e30f; gl[gbase + tid] = 0.f; }
        return;
    }

    {
        int t = tid >> 6, d = tid & 63;
        qs[t][d] = q[((size_t)(b * T + t) * E) + h * D + d];
    }
    __syncthreads();

    const float scale = 0.125f;
    for (int i = tid; i < len; i += 256) {
        int s = s0 + i;
        size_t off = ((size_t)b * L + s) * E + h * D;
        bool old = (s < pos);
        const float4* kr = (const float4*)((old ? kin : kout) + off);
        float d0 = 0.f, d1 = 0.f, d2 = 0.f, d3 = 0.f;
        #pragma unroll
        for (int i4 = 0; i4 < 16; i4++) {
            float4 kv = kr[i4];
            if (old) {
                kv.x = isnan(kv.x) ? 0.f : kv.x;
                kv.y = isnan(kv.y) ? 0.f : kv.y;
                kv.z = isnan(kv.z) ? 0.f : kv.z;
                kv.w = isnan(kv.w) ? 0.f : kv.w;
            }
            int d = i4 * 4;
            d0 += qs[0][d]*kv.x + qs[0][d+1]*kv.y + qs[0][d+2]*kv.z + qs[0][d+3]*kv.w;
            d1 += qs[1][d]*kv.x + qs[1][d+1]*kv.y + qs[1][d+2]*kv.z + qs[1][d+3]*kv.w;
            d2 += qs[2][d]*kv.x + qs[2][d+1]*kv.y + qs[2][d+2]*kv.z + qs[2][d+3]*kv.w;
            d3 += qs[3][d]*kv.x + qs[3][d+1]*kv.y + qs[3][d+2]*kv.z + qs[3][d+3]*kv.w;
        }
        sc[0][i] = (s <= pos + 0) ? d0 * scale : -1e30f;
        sc[1][i] = (s <= pos + 1) ? d1 * scale : -1e30f;
        sc[2][i] = (s <= pos + 2) ? d2 * scale : -1e30f;
        sc[3][i] = (s <= pos + 3) ? d3 * scale : -1e30f;
    }
    __syncthreads();

    #pragma unroll
    for (int t = 0; t < 4; t++) {
        float m = -1e30f;
        for (int i = tid; i < len; i += 256) m = fmaxf(m, sc[t][i]);
        #pragma unroll
        for (int o = 16; o > 0; o >>= 1) m = fmaxf(m, __shfl_xor_sync(0xffffffffu, m, o));
        if ((tid & 31) == 0) red[tid >> 5] = m;
        __syncthreads();
        m = fmaxf(fmaxf(fmaxf(red[0], red[1]), fmaxf(red[2], red[3])),
                  fmaxf(fmaxf(red[4], red[5]), fmaxf(red[6], red[7])));
        float ssum = 0.f;
        for (int i = tid; i < len; i += 256) {
            float e = __expf(sc[t][i] - m);
            sc[t][i] = e;
            ssum += e;
        }
        #pragma unroll
        for (int o = 16; o > 0; o >>= 1) ssum += __shfl_xor_sync(0xffffffffu, ssum, o);
        __syncthreads();
        if ((tid & 31) == 0) red[tid >> 5] = ssum;
        __syncthreads();
        if (tid == 0) {
            mt[t] = m;
            lt[t] = red[0]+red[1]+red[2]+red[3]+red[4]+red[5]+red[6]+red[7];
        }
        __syncthreads();
    }

    {
        int sg = tid >> 6, d = tid & 63;
        int q4 = (len + 3) >> 2;
        int i0 = sg * q4;
        int i1 = min(len, i0 + q4);
        float a0 = 0.f, a1 = 0.f, a2 = 0.f, a3 = 0.f;
        for (int i = i0; i < i1; i++) {
            int s = s0 + i;
            bool old = (s < pos);
            float v0 = (old ? vin : vout)[((size_t)b * L + s) * E + h * D + d];
            if (old) v0 = isnan(v0) ? 0.f : v0;
            a0 += sc[0][i] * v0;
            a1 += sc[1][i] * v0;
            a2 += sc[2][i] * v0;
            a3 += sc[3][i] * v0;
        }
        vpart[sg][0][d] = a0;
        vpart[sg][1][d] = a1;
        vpart[sg][2][d] = a2;
        vpart[sg][3][d] = a3;
    }
    __syncthreads();
    {
        int t = tid >> 6, d = tid & 63;
        float sum = vpart[0][t][d] + vpart[1][t][d] + vpart[2][t][d] + vpart[3][t][d];
        po[((size_t)(gbase + t)) * 64 + d] = sum;
        if (tid < 4) { gm[gbase + tid] = mt[tid]; gl[gbase + tid] = lt[tid]; }
    }
}

// -------- Attention combine --------
__global__ void attn_comb_kernel(const float* __restrict__ po,
                                 const float* __restrict__ gm,
                                 const float* __restrict__ gl,
                                 float* __restrict__ out)
{
    int bh = blockIdx.x;
    int b = bh >> 4, h = bh & 15;
    int tid = threadIdx.x;
    int t = tid >> 6, d = tid & 63;

    float m0 = gm[(bh * 4 + 0) * 4 + t];
    float m1 = gm[(bh * 4 + 1) * 4 + t];
    float m2 = gm[(bh * 4 + 2) * 4 + t];
    float m3 = gm[(bh * 4 + 3) * 4 + t];
    float M = fmaxf(fmaxf(m0, m1), fmaxf(m2, m3));
    float w0 = __expf(m0 - M), w1 = __expf(m1 - M);
    float w2 = __expf(m2 - M), w3 = __expf(m3 - M);
    float l = w0 * gl[(bh * 4 + 0) * 4 + t] + w1 * gl[(bh * 4 + 1) * 4 + t]
            + w2 * gl[(bh * 4 + 2) * 4 + t] + w3 * gl[(bh * 4 + 3) * 4 + t];
    float o = w0 * po[((size_t)(bh * 4 + 0) * 4 + t) * 64 + d]
            + w1 * po[((size_t)(bh * 4 + 1) * 4 + t) * 64 + d]
            + w2 * po[((size_t)(bh * 4 + 2) * 4 + t) * 64 + d]
            + w3 * po[((size_t)(bh * 4 + 3) * 4 + t) * 64 + d];
    out[((size_t)(b * T + t) * E) + h * D + d] = o / l;
}

extern "C" void kernel_launch(void* const* d_in, const int* in_sizes, int n_in,
                              void* d_out, int out_size)
{
    const float* seq       = (const float*)d_in[0];
    const float* bos       = (const float*)d_in[1];
    const float* caches    = (const float*)d_in[2];
    const int*   positions = (const int*)  d_in[3];
    const float* in_w      = (const float*)d_in[4];
    const float* ip_w      = (const float*)d_in[5];
    const float* op_w      = (const float*)d_in[6];
    const float* n1w       = (const float*)d_in[7];
    const float* n1b       = (const float*)d_in[8];
    const float* n2w       = (const float*)d_in[9];
    const float* n2b       = (const float*)d_in[10];
    const float* l1_w      = (const float*)d_in[11];
    const float* l2_w      = (const float*)d_in[12];
    const float* on_w      = (const float*)d_in[13];
    const float* on_b      = (const float*)d_in[14];
    const float* eos_w     = (const float*)d_in[15];
    const float* eos_b     = (const float*)d_in[16];

    float* out = (float*)d_out;
    const size_t cache_elems = (size_t)NL * 2 * B * L * E;
    float* out_x     = out;
    float* out_eos   = out + (size_t)NTOK * E;
    float* out_cache = out_eos + NTOK;
    float* out_pos   = out_cache + cache_elems;

    float *px, *pxn, *pq, *pattn, *ppart, *ppart2, *pseq, *ppo, *pm, *pl;
    cudaGetSymbolAddress((void**)&px,     g_x);
    cudaGetSymbolAddress((void**)&pxn,    g_xn);
    cudaGetSymbolAddress((void**)&pq,     g_q);
    cudaGetSymbolAddress((void**)&pattn,  g_attn);
    cudaGetSymbolAddress((void**)&ppart,  g_part);
    cudaGetSymbolAddress((void**)&ppart2, g_part2);
    cudaGetSymbolAddress((void**)&pseq,   g_seq);
    cudaGetSymbolAddress((void**)&ppo,    g_po);
    cudaGetSymbolAddress((void**)&pm,     g_m);
    cudaGetSymbolAddress((void**)&pl,     g_l);

    // serial bulk copy (big grid, near BW floor)
    cache_copy_kernel<<<(unsigned)((CACHE_F4 + 255) / 256), 256>>>(
        (const float4*)caches, (float4*)out_cache, positions);

    prep_pos_kernel<<<5, 256>>>(seq, bos, positions, pseq, out_pos);
    gemv64_kernel<0,1><<<E / 64, 256>>>(pseq, in_w, px, nullptr, INDIM, E);
    ln_kernel<<<NTOK, 256>>>(px, n1w, n1b, pxn);

    for (int i = 0; i < NL; i++) {
        const float* ipw = ip_w + (size_t)i * 3 * E * E;
        const float* opw = op_w + (size_t)i * E * E;
        const float* l1  = l1_w + (size_t)i * FF * E;
        const float* l2  = l2_w + (size_t)i * E * FF;
        float* kcache = out_cache + ((size_t)i * 2 + 0) * B * L * E;
        float* vcache = out_cache + ((size_t)i * 2 + 1) * B * L * E;
        const float* kcin = caches + ((size_t)i * 2 + 0) * B * L * E;
        const float* vcin = caches + ((size_t)i * 2 + 1) * B * L * E;
        const int* posl = positions + i * B;

        // qkv: K=1024, N=3072, split-K=8 -> 384 blocks (Kc=128, 4 chunks)
        gemv64_kernel<0,8><<<dim3(3 * E / 64, 8), 256>>>(pxn, ipw, nullptr, ppart2, E, 3 * E);
        reduce_rope_kernel<<<192, 256>>>(ppart2, posl, pq, kcache, vcache);

        attn_part_kernel<<<512, 256>>>(pq, kcin, vcin, kcache, vcache, posl, ppo, pm, pl);
        attn_comb_kernel<<<B * H, 256>>>(ppo, pm, pl, pattn);

        // op: K=1024, N=1024, split-K=16 -> 256 blocks (Kc=64, 2 chunks)
        gemv64_kernel<0,16><<<dim3(E / 64, 16), 256>>>(pattn, opw, nullptr, ppart2, E, E);
        reduce_ln_kernel<16><<<NTOK, 256>>>(ppart2, px, n2w + (size_t)i * E, n2b + (size_t)i * E, pxn);

        // l1: K=1024, N=4096, split-K=4 -> 256 blocks (Kc=256, 8 chunks)
        gemv64_kernel<0,4><<<dim3(FF / 64, 4), 256>>>(pxn, l1, nullptr, ppart, E, FF);

        // l2: K=4096, N=1024, split-K=16, gelu(sum of 4 partials) on X load -> 256 blocks
        gemv64_kernel<4,16><<<dim3(E / 64, 16), 256>>>(ppart, l2, nullptr, ppart2, FF, E);

        if (i + 1 < NL) {
            reduce_ln_kernel<16><<<NTOK, 256>>>(ppart2, px,
                                                n1w + (size_t)(i + 1) * E,
                                                n1b + (size_t)(i + 1) * E, pxn);
        } else {
            reduce_ln_eos_kernel<<<NTOK, 256>>>(ppart2, px, on_w, on_b,
                                                eos_w, eos_b, out_x, out_eos);
        }
    }
}

// round 11
// speedup vs baseline: 1.2736x; 1.0849x over previous
#include <cuda_runtime.h>
#include <math.h>

#define NL 6
#define B  8
#define T  4
#define L  2048
#define H  16
#define D  64
#define E  1024
#define FF 4096
#define INDIM 32
#define NTOK 32
#define DEPTH 3

#define CACHE_F4 50331648LL            // NL*2*B*L*E/4

// -------- scratch (device globals) --------
__device__ __align__(16) float g_x   [NTOK * E];
__device__ __align__(16) float g_xn  [NTOK * E];
__device__ __align__(16) float g_q   [NTOK * E];
__device__ __align__(16) float g_attn[NTOK * E];
__device__ __align__(16) float g_h   [NTOK * FF];
__device__ __align__(16) float g_seq [NTOK * INDIM];
__device__ __align__(16) float g_part[524288];
__device__ __align__(16) float g_po  [B * H * 4 * T * D];
__device__ float g_m [B * H * 4 * T];
__device__ float g_l [B * H * 4 * T];

// -------- f32x2 helpers --------
__device__ __forceinline__ void fma2(unsigned long long& d,
                                     unsigned long long a,
                                     unsigned long long b) {
    asm("fma.rn.f32x2 %0, %1, %2, %3;" : "=l"(d) : "l"(a), "l"(b), "l"(d));
}
__device__ __forceinline__ float2 upk(unsigned long long v) {
    float2 f;
    asm("mov.b64 {%0, %1}, %2;" : "=f"(f.x), "=f"(f.y) : "l"(v));
    return f;
}
__device__ __forceinline__ void cpa16(unsigned dst, const void* src) {
    asm volatile("cp.async.ca.shared.global [%0], [%1], 16;" :: "r"(dst), "l"(src));
}
#define CP_COMMIT() asm volatile("cp.async.commit_group;")
#define CP_WAIT1()  asm volatile("cp.async.wait_group 1;")

// -------- bulk cache copy with NaN cleaning (full range, runs first) --------
__global__ void cache_copy_kernel(const float4* __restrict__ in,
                                  float4* __restrict__ out, long n)
{
    long i = (long)blockIdx.x * blockDim.x + threadIdx.x;
    if (i < n) {
        float4 v = in[i];
        v.x = isnan(v.x) ? 0.0f : v.x;
        v.y = isnan(v.y) ? 0.0f : v.y;
        v.z = isnan(v.z) ? 0.0f : v.z;
        v.w = isnan(v.w) ? 0.0f : v.w;
        out[i] = v;
    }
}

// -------- prep seq (NaN->bos) + new positions --------
__global__ void prep_pos_kernel(const float* __restrict__ seq,
                                const float* __restrict__ bos,
                                const int* __restrict__ positions,
                                float* __restrict__ out_seq,
                                float* __restrict__ out_pos)
{
    if (blockIdx.x < 4) {
        int i = blockIdx.x * 256 + threadIdx.x;
        float v = seq[i];
        out_seq[i] = isnan(v) ? bos[i & (INDIM - 1)] : v;
    } else {
        int i = threadIdx.x;
        if (i < NL * B) out_pos[i] = (float)(positions[i] + T);
    }
}

// ======== GEMM: Y[32,N] = X[32,K] @ W[N,K]^T ========
// cp.async 3-stage pipeline, f32x2 compute. 64 cols/block, 8 warps, lane=row.
// KSPLIT==1: direct store to Y. Else partials.
template<int KSPLIT>
__global__ void gemv_kernel(const float* __restrict__ X,
                            const float* __restrict__ W,
                            float* __restrict__ Y,
                            float* __restrict__ part,
                            int K, int N)
{
    __shared__ __align__(16) float Xs[DEPTH][32][36];
    __shared__ __align__(16) float Ws[DEPTH][64][36];

    const int t    = threadIdx.x;
    const int lane = t & 31;
    const int c0   = (t >> 5) * 8;
    const int n0   = blockIdx.x * 64;
    const int Kc   = K / KSPLIT;
    const int kbase = blockIdx.y * Kc;
    const int nch  = Kc >> 5;

    const int xrow = t >> 3, xk4 = (t & 7) * 4;
    const int wrow = t >> 2, wk  = (t & 3) * 8;

    const float* xsrc = X + (size_t)xrow * K + kbase + xk4;
    const float* wsrc = W + (size_t)(n0 + wrow) * K + kbase + wk;

    const unsigned xbase = (unsigned)__cvta_generic_to_shared(&Xs[0][0][0])
                         + (unsigned)((xrow * 36 + xk4) * 4);
    const unsigned wbase = (unsigned)__cvta_generic_to_shared(&Ws[0][0][0])
                         + (unsigned)((wrow * 36 + wk) * 4);
    const unsigned XST = 32 * 36 * 4;
    const unsigned WST = 64 * 36 * 4;

    // preload stages 0..DEPTH-2
    #pragma unroll
    for (int p = 0; p < DEPTH - 1; p++) {
        if (p < nch) {
            cpa16(xbase + p * XST, xsrc + (size_t)p * 32);
            cpa16(wbase + p * WST, wsrc + (size_t)p * 32);
            cpa16(wbase + p * WST + 16, wsrc + (size_t)p * 32 + 4);
        }
        CP_COMMIT();
    }

    unsigned long long acc[8];
    #pragma unroll
    for (int c = 0; c < 8; c++) acc[c] = 0ULL;

    int st = 0;                 // buffer of current chunk
    int si = (DEPTH - 1) % DEPTH;  // buffer to refill this iteration
    for (int ch = 0; ch < nch; ch++) {
        CP_WAIT1();
        __syncthreads();

        #pragma unroll
        for (int p = 0; p < 16; p += 2) {
            unsigned long long x0 = *(const unsigned long long*)&Xs[st][lane][2 * p];
            unsigned long long x1 = *(const unsigned long long*)&Xs[st][lane][2 * p + 2];
            #pragma unroll
            for (int c = 0; c < 8; c++) {
                longlong2 w = *(const longlong2*)&Ws[st][c0 + c][2 * p];
                fma2(acc[c], x0, (unsigned long long)w.x);
                fma2(acc[c], x1, (unsigned long long)w.y);
            }
        }
        __syncthreads();

        int nc = ch + DEPTH - 1;
        if (nc < nch) {
            cpa16(xbase + si * XST, xsrc + (size_t)nc * 32);
            cpa16(wbase + si * WST, wsrc + (size_t)nc * 32);
            cpa16(wbase + si * WST + 16, wsrc + (size_t)nc * 32 + 4);
        }
        CP_COMMIT();
        st = (st == DEPTH - 1) ? 0 : st + 1;
        si = (si == DEPTH - 1) ? 0 : si + 1;
    }

    if (KSPLIT == 1) {
        #pragma unroll
        for (int c = 0; c < 8; c++) {
            float2 p = upk(acc[c]);
            Y[(size_t)lane * N + n0 + c0 + c] = p.x + p.y;
        }
    } else {
        float* pp = part + ((size_t)blockIdx.y * 32 + lane) * N + n0 + c0;
        #pragma unroll
        for (int c = 0; c < 8; c++) {
            float2 p = upk(acc[c]);
            pp[c] = p.x + p.y;
        }
    }
}

// sum split-K partials, optional gelu / accumulate
template<int ACT, int ACC, int KS>
__global__ void reduce_kernel(const float* __restrict__ part,
                              float* __restrict__ Y, int N)
{
    int i = blockIdx.x * 256 + threadIdx.x;
    if (i >= 32 * N) return;
    int r = i / N, n = i - r * N;
    float s = 0.f;
    #pragma unroll
    for (int k = 0; k < KS; k++) s += part[((size_t)k * 32 + r) * N + n];
    if (ACT == 1) s = 0.5f * s * (1.0f + erff(s * 0.70710678118654752f));
    if (ACC) Y[i] += s; else Y[i] = s;
}

// -------- fused qkv split-K(4) reduce + RoPE + cache scatter --------
__global__ void reduce_rope_kernel(const float* __restrict__ part,
                                   const int* __restrict__ pos_l,
                                   float* __restrict__ qout,
                                   float* __restrict__ kcache,
                                   float* __restrict__ vcache)
{
    int id = blockIdx.x * 256 + threadIdx.x;  // 49152 pairs
    int tok = id / 1536;
    int f   = (id - tok * 1536) * 2;
    float s0 = 0.f, s1 = 0.f;
    #pragma unroll
    for (int k = 0; k < 4; k++) {
        const float* p = part + ((size_t)(k * 32 + tok) * 3072) + f;
        s0 += p[0];
        s1 += p[1];
    }
    int b = tok >> 2, t = tok & 3;
    int pos = pos_l[b];
    if (f < E) {
        int j = (f & 63) >> 1;
        float freq = __expf(-(float)j * (logf(10000.0f) / 32.0f));
        float sn, cs;
        sincosf((float)(pos + t) * freq, &sn, &cs);
        qout[(size_t)tok * E + f]     = s0 * cs - s1 * sn;
        qout[(size_t)tok * E + f + 1] = s0 * sn + s1 * cs;
    } else if (f < 2 * E) {
        int fk = f - E;
        int j = (fk & 63) >> 1;
        float freq = __expf(-(float)j * (logf(10000.0f) / 32.0f));
        float sn, cs;
        sincosf((float)(pos + t) * freq, &sn, &cs);
        int slot = (pos + t) % L;
        size_t off = ((size_t)b * L + slot) * E + fk;
        kcache[off]     = s0 * cs - s1 * sn;
        kcache[off + 1] = s0 * sn + s1 * cs;
    } else {
        int fv = f - 2 * E;
        int slot = (pos + t) % L;
        size_t off = ((size_t)b * L + slot) * E + fv;
        vcache[off]     = s0;
        vcache[off + 1] = s1;
    }
}

// -------- LayerNorm, one block(256) per token --------
__global__ void ln_kernel(const float* __restrict__ X,
                          const float* __restrict__ w,
                          const float* __restrict__ b,
                          float* __restrict__ Y)
{
    int tok = blockIdx.x;
    int tid = threadIdx.x;
    const float* x = X + (size_t)tok * E;
    float v[4];
    #pragma unroll
    for (int j = 0; j < 4; j++) v[j] = x[tid + 256 * j];
    float s = v[0] + v[1] + v[2] + v[3];
    #pragma unroll
    for (int o = 16; o > 0; o >>= 1) s += __shfl_xor_sync(0xffffffffu, s, o);
    __shared__ float ws[8];
    if ((tid & 31) == 0) ws[tid >> 5] = s;
    __syncthreads();
    float mean = (ws[0]+ws[1]+ws[2]+ws[3]+ws[4]+ws[5]+ws[6]+ws[7]) * (1.0f / E);
    float s2 = 0.f;
    #pragma unroll
    for (int j = 0; j < 4; j++) { float d = v[j] - mean; s2 += d * d; }
    #pragma unroll
    for (int o = 16; o > 0; o >>= 1) s2 += __shfl_xor_sync(0xffffffffu, s2, o);
    __syncthreads();
    if ((tid & 31) == 0) ws[tid >> 5] = s2;
    __syncthreads();
    float var = (ws[0]+ws[1]+ws[2]+ws[3]+ws[4]+ws[5]+ws[6]+ws[7]) * (1.0f / E);
    float r = rsqrtf(var + 1e-5f);
    #pragma unroll
    for (int j = 0; j < 4; j++) {
        int idx = tid + 256 * j;
        Y[(size_t)tok * E + idx] = (v[j] - mean) * r * w[idx] + b[idx];
    }
}

// -------- final LayerNorm fused with eos dot --------
__global__ void ln_eos_kernel(const float* __restrict__ X,
                              const float* __restrict__ w,
                              const float* __restrict__ b,
                              const float* __restrict__ ew,
                              const float* __restrict__ eb,
                              float* __restrict__ Y,
                              float* __restrict__ out_eos)
{
    int tok = blockIdx.x;
    int tid = threadIdx.x;
    const float* x = X + (size_t)tok * E;
    float v[4];
    #pragma unroll
    for (int j = 0; j < 4; j++) v[j] = x[tid + 256 * j];
    float s = v[0] + v[1] + v[2] + v[3];
    #pragma unroll
    for (int o = 16; o > 0; o >>= 1) s += __shfl_xor_sync(0xffffffffu, s, o);
    __shared__ float ws[8];
    if ((tid & 31) == 0) ws[tid >> 5] = s;
    __syncthreads();
    float mean = (ws[0]+ws[1]+ws[2]+ws[3]+ws[4]+ws[5]+ws[6]+ws[7]) * (1.0f / E);
    float s2 = 0.f;
    #pragma unroll
    for (int j = 0; j < 4; j++) { float d = v[j] - mean; s2 += d * d; }
    #pragma unroll
    for (int o = 16; o > 0; o >>= 1) s2 += __shfl_xor_sync(0xffffffffu, s2, o);
    __syncthreads();
    if ((tid & 31) == 0) ws[tid >> 5] = s2;
    __syncthreads();
    float var = (ws[0]+ws[1]+ws[2]+ws[3]+ws[4]+ws[5]+ws[6]+ws[7]) * (1.0f / E);
    float r = rsqrtf(var + 1e-5f);
    float ed = 0.f;
    #pragma unroll
    for (int j = 0; j < 4; j++) {
        int idx = tid + 256 * j;
        float y = (v[j] - mean) * r * w[idx] + b[idx];
        Y[(size_t)tok * E + idx] = y;
        ed += y * ew[idx];
    }
    #pragma unroll
    for (int o = 16; o > 0; o >>= 1) ed += __shfl_xor_sync(0xffffffffu, ed, o);
    __syncthreads();
    if ((tid & 31) == 0) ws[tid >> 5] = ed;
    __syncthreads();
    if (tid == 0)
        out_eos[tok] = ws[0]+ws[1]+ws[2]+ws[3]+ws[4]+ws[5]+ws[6]+ws[7] + eb[0];
}

// -------- Attention partial: grid 512, K/V from output cache --------
#define CMAX 260
__global__ void attn_part_kernel(const float* __restrict__ q,
                                 const float* __restrict__ kc,
                                 const float* __restrict__ vc,
                                 const int* __restrict__ pos_l,
                                 float* __restrict__ po,
                                 float* __restrict__ gm,
                                 float* __restrict__ gl)
{
    __shared__ float qs[4][64];
    __shared__ float sc[4][CMAX];
    __shared__ float red[8];
    __shared__ float mt[4], lt[4];
    __shared__ float vpart[4][4][64];

    int bh   = blockIdx.x & 127;
    int cidx = blockIdx.x >> 7;
    int b = bh >> 4, h = bh & 15;
    int tid = threadIdx.x;
    int pos = pos_l[b];
    int slen = pos + T;
    int chunk = (slen + 3) >> 2;
    int s0 = cidx * chunk;
    int s1 = min(slen, s0 + chunk);
    int len = s1 - s0;
    int gbase = (bh * 4 + cidx) * 4;

    if (len <= 0) {
        po[(size_t)gbase * 64 + tid] = 0.f;
        if (tid < 4) { gm[gbase + tid] = -1e30f; gl[gbase + tid] = 0.f; }
        return;
    }

    {
        int t = tid >> 6, d = tid & 63;
        qs[t][d] = q[((size_t)(b * T + t) * E) + h * D + d];
    }
    __syncthreads();

    const float scale = 0.125f;
    for (int i = tid; i < len; i += 256) {
        int s = s0 + i;
        const float4* kr = (const float4*)(kc + ((size_t)b * L + s) * E + h * D);
        float d0 = 0.f, d1 = 0.f, d2 = 0.f, d3 = 0.f;
        #pragma unroll
        for (int i4 = 0; i4 < 16; i4++) {
            float4 kv = kr[i4];
            int d = i4 * 4;
            d0 += qs[0][d]*kv.x + qs[0][d+1]*kv.y + qs[0][d+2]*kv.z + qs[0][d+3]*kv.w;
            d1 += qs[1][d]*kv.x + qs[1][d+1]*kv.y + qs[1][d+2]*kv.z + qs[1][d+3]*kv.w;
            d2 += qs[2][d]*kv.x + qs[2][d+1]*kv.y + qs[2][d+2]*kv.z + qs[2][d+3]*kv.w;
            d3 += qs[3][d]*kv.x + qs[3][d+1]*kv.y + qs[3][d+2]*kv.z + qs[3][d+3]*kv.w;
        }
        sc[0][i] = (s <= pos + 0) ? d0 * scale : -1e30f;
        sc[1][i] = (s <= pos + 1) ? d1 * scale : -1e30f;
        sc[2][i] = (s <= pos + 2) ? d2 * scale : -1e30f;
        sc[3][i] = (s <= pos + 3) ? d3 * scale : -1e30f;
    }
    __syncthreads();

    #pragma unroll
    for (int t = 0; t < 4; t++) {
        float m = -1e30f;
        for (int i = tid; i < len; i += 256) m = fmaxf(m, sc[t][i]);
        #pragma unroll
        for (int o = 16; o > 0; o >>= 1) m = fmaxf(m, __shfl_xor_sync(0xffffffffu, m, o));
        if ((tid & 31) == 0) red[tid >> 5] = m;
        __syncthreads();
        m = fmaxf(fmaxf(fmaxf(red[0], red[1]), fmaxf(red[2], red[3])),
                  fmaxf(fmaxf(red[4], red[5]), fmaxf(red[6], red[7])));
        float ssum = 0.f;
        for (int i = tid; i < len; i += 256) {
            float e = __expf(sc[t][i] - m);
            sc[t][i] = e;
            ssum += e;
        }
        #pragma unroll
        for (int o = 16; o > 0; o >>= 1) ssum += __shfl_xor_sync(0xffffffffu, ssum, o);
        __syncthreads();
        if ((tid & 31) == 0) red[tid >> 5] = ssum;
        __syncthreads();
        if (tid == 0) {
            mt[t] = m;
            lt[t] = red[0]+red[1]+red[2]+red[3]+red[4]+red[5]+red[6]+red[7];
        }
        __syncthreads();
    }

    {
        int sg = tid >> 6, d = tid & 63;
        int q4 = (len + 3) >> 2;
        int i0 = sg * q4;
        int i1 = min(len, i0 + q4);
        const float* vp = vc + ((size_t)b * L + s0) * E + h * D + d;
        float a0 = 0.f, a1 = 0.f, a2 = 0.f, a3 = 0.f;
        int i = i0;
        for (; i + 2 <= i1; i += 2) {
            float v0 = vp[(size_t)i * E];
            float v1 = vp[(size_t)(i + 1) * E];
            a0 += sc[0][i] * v0 + sc[0][i+1] * v1;
            a1 += sc[1][i] * v0 + sc[1][i+1] * v1;
            a2 += sc[2][i] * v0 + sc[2][i+1] * v1;
            a3 += sc[3][i] * v0 + sc[3][i+1] * v1;
        }
        if (i < i1) {
            float v0 = vp[(size_t)i * E];
            a0 += sc[0][i] * v0;
            a1 += sc[1][i] * v0;
            a2 += sc[2][i] * v0;
            a3 += sc[3][i] * v0;
        }
        vpart[sg][0][d] = a0;
        vpart[sg][1][d] = a1;
        vpart[sg][2][d] = a2;
        vpart[sg][3][d] = a3;
    }
    __syncthreads();
    {
        int t = tid >> 6, d = tid & 63;
        float sum = vpart[0][t][d] + vpart[1][t][d] + vpart[2][t][d] + vpart[3][t][d];
        po[((size_t)(gbase + t)) * 64 + d] = sum;
        if (tid < 4) { gm[gbase + tid] = mt[tid]; gl[gbase + tid] = lt[tid]; }
    }
}

// -------- Attention combine --------
__global__ void attn_comb_kernel(const float* __restrict__ po,
                                 const float* __restrict__ gm,
                                 const float* __restrict__ gl,
                                 float* __restrict__ out)
{
    int bh = blockIdx.x;
    int b = bh >> 4, h = bh & 15;
    int tid = threadIdx.x;
    int t = tid >> 6, d = tid & 63;

    float m0 = gm[(bh * 4 + 0) * 4 + t];
    float m1 = gm[(bh * 4 + 1) * 4 + t];
    float m2 = gm[(bh * 4 + 2) * 4 + t];
    float m3 = gm[(bh * 4 + 3) * 4 + t];
    float M = fmaxf(fmaxf(m0, m1), fmaxf(m2, m3));
    float w0 = __expf(m0 - M), w1 = __expf(m1 - M);
    float w2 = __expf(m2 - M), w3 = __expf(m3 - M);
    float l = w0 * gl[(bh * 4 + 0) * 4 + t] + w1 * gl[(bh * 4 + 1) * 4 + t]
            + w2 * gl[(bh * 4 + 2) * 4 + t] + w3 * gl[(bh * 4 + 3) * 4 + t];
    float o = w0 * po[((size_t)(bh * 4 + 0) * 4 + t) * 64 + d]
            + w1 * po[((size_t)(bh * 4 + 1) * 4 + t) * 64 + d]
            + w2 * po[((size_t)(bh * 4 + 2) * 4 + t) * 64 + d]
            + w3 * po[((size_t)(bh * 4 + 3) * 4 + t) * 64 + d];
    out[((size_t)(b * T + t) * E) + h * D + d] = o / l;
}

extern "C" void kernel_launch(void* const* d_in, const int* in_sizes, int n_in,
                              void* d_out, int out_size)
{
    const float* seq       = (const float*)d_in[0];
    const float* bos       = (const float*)d_in[1];
    const float* caches    = (const float*)d_in[2];
    const int*   positions = (const int*)  d_in[3];
    const float* in_w      = (const float*)d_in[4];
    const float* ip_w      = (const float*)d_in[5];
    const float* op_w      = (const float*)d_in[6];
    const float* n1w       = (const float*)d_in[7];
    const float* n1b       = (const float*)d_in[8];
    const float* n2w       = (const float*)d_in[9];
    const float* n2b       = (const float*)d_in[10];
    const float* l1_w      = (const float*)d_in[11];
    const float* l2_w      = (const float*)d_in[12];
    const float* on_w      = (const float*)d_in[13];
    const float* on_b      = (const float*)d_in[14];
    const float* eos_w     = (const float*)d_in[15];
    const float* eos_b     = (const float*)d_in[16];

    float* out = (float*)d_out;
    const size_t cache_elems = (size_t)NL * 2 * B * L * E;
    float* out_x     = out;
    float* out_eos   = out + (size_t)NTOK * E;
    float* out_cache = out_eos + NTOK;
    float* out_pos   = out_cache + cache_elems;

    float *px, *pxn, *pq, *pattn, *ph, *pseq, *ppart, *ppo, *pm, *pl;
    cudaGetSymbolAddress((void**)&px,    g_x);
    cudaGetSymbolAddress((void**)&pxn,   g_xn);
    cudaGetSymbolAddress((void**)&pq,    g_q);
    cudaGetSymbolAddress((void**)&pattn, g_attn);
    cudaGetSymbolAddress((void**)&ph,    g_h);
    cudaGetSymbolAddress((void**)&pseq,  g_seq);
    cudaGetSymbolAddress((void**)&ppart, g_part);
    cudaGetSymbolAddress((void**)&ppo,   g_po);
    cudaGetSymbolAddress((void**)&pm,    g_m);
    cudaGetSymbolAddress((void**)&pl,    g_l);

    long nf4 = (long)(cache_elems / 4);
    cache_copy_kernel<<<(unsigned)((nf4 + 255) / 256), 256>>>((const float4*)caches,
                                                              (float4*)out_cache, nf4);

    prep_pos_kernel<<<5, 256>>>(seq, bos, positions, pseq, out_pos);
    gemv_kernel<1><<<dim3(E / 64, 1), 256>>>(pseq, in_w, px, nullptr, INDIM, E);

    for (int i = 0; i < NL; i++) {
        const float* ipw = ip_w + (size_t)i * 3 * E * E;
        const float* opw = op_w + (size_t)i * E * E;
        const float* l1  = l1_w + (size_t)i * FF * E;
        const float* l2  = l2_w + (size_t)i * E * FF;
        float* kcache = out_cache + ((size_t)i * 2 + 0) * B * L * E;
        float* vcache = out_cache + ((size_t)i * 2 + 1) * B * L * E;
        const int* posl = positions + i * B;

        ln_kernel<<<NTOK, 256>>>(px, n1w + (size_t)i * E, n1b + (size_t)i * E, pxn);

        // qkv: K=1024, N=3072, split-K=4 -> 192 blocks
        gemv_kernel<4><<<dim3(3 * E / 64, 4), 256>>>(pxn, ipw, nullptr, ppart, E, 3 * E);
        reduce_rope_kernel<<<192, 256>>>(ppart, posl, pq, kcache, vcache);

        attn_part_kernel<<<512, 256>>>(pq, kcache, vcache, posl, ppo, pm, pl);
        attn_comb_kernel<<<B * H, 256>>>(ppo, pm, pl, pattn);

        // op: K=1024, N=1024, split-K=8 -> 128 blocks, accumulate into x
        gemv_kernel<8><<<dim3(E / 64, 8), 256>>>(pattn, opw, nullptr, ppart, E, E);
        reduce_kernel<0,1,8><<<(32 * E + 255) / 256, 256>>>(ppart, px, E);

        ln_kernel<<<NTOK, 256>>>(px, n2w + (size_t)i * E, n2b + (size_t)i * E, pxn);

        // l1: K=1024, N=4096, split-K=2 -> 128 blocks; gelu in reduce
        gemv_kernel<2><<<dim3(FF / 64, 2), 256>>>(pxn, l1, nullptr, ppart, E, FF);
        reduce_kernel<1,0,2><<<(32 * FF + 255) / 256, 256>>>(ppart, ph, FF);

        // l2: K=4096, N=1024, split-K=8 -> 128 blocks, accumulate into x
        gemv_kernel<8><<<dim3(E / 64, 8), 256>>>(ph, l2, nullptr, ppart, FF, E);
        reduce_kernel<0,1,8><<<(32 * E + 255) / 256, 256>>>(ppart, px, E);
    }

    ln_eos_kernel<<<NTOK, 256>>>(px, on_w, on_b, eos_w, eos_b, out_x, out_eos);
}

// round 12
// speedup vs baseline: 1.3434x; 1.0547x over previous
#include <cuda_runtime.h>
#include <math.h>

#define NL 6
#define B  8
#define T  4
#define L  2048
#define H  16
#define D  64
#define E  1024
#define FF 4096
#define INDIM 32
#define NTOK 32
#define DEPTH 3

#define CACHE_F4 50331648LL            // NL*2*B*L*E/4

#define GDW() asm volatile("griddepcontrol.wait;" ::: "memory")

// -------- scratch (device globals) --------
__device__ __align__(16) float g_x   [NTOK * E];
__device__ __align__(16) float g_xn  [NTOK * E];
__device__ __align__(16) float g_q   [NTOK * E];
__device__ __align__(16) float g_attn[NTOK * E];
__device__ __align__(16) float g_h   [NTOK * FF];
__device__ __align__(16) float g_seq [NTOK * INDIM];
__device__ __align__(16) float g_part[524288];
__device__ __align__(16) float g_po  [B * H * 4 * T * D];
__device__ float g_m [B * H * 4 * T];
__device__ float g_l [B * H * 4 * T];

// -------- f32x2 helpers --------
__device__ __forceinline__ void fma2(unsigned long long& d,
                                     unsigned long long a,
                                     unsigned long long b) {
    asm("fma.rn.f32x2 %0, %1, %2, %3;" : "=l"(d) : "l"(a), "l"(b), "l"(d));
}
__device__ __forceinline__ float2 upk(unsigned long long v) {
    float2 f;
    asm("mov.b64 {%0, %1}, %2;" : "=f"(f.x), "=f"(f.y) : "l"(v));
    return f;
}
__device__ __forceinline__ void cpa16(unsigned dst, const void* src) {
    asm volatile("cp.async.ca.shared.global [%0], [%1], 16;" :: "r"(dst), "l"(src));
}
#define CP_COMMIT() asm volatile("cp.async.commit_group;")
#define CP_WAIT1()  asm volatile("cp.async.wait_group 1;")

// -------- bulk cache copy with NaN cleaning (full range, runs first) --------
__global__ void cache_copy_kernel(const float4* __restrict__ in,
                                  float4* __restrict__ out, long n)
{
    long i = (long)blockIdx.x * blockDim.x + threadIdx.x;
    if (i < n) {
        float4 v = in[i];
        v.x = isnan(v.x) ? 0.0f : v.x;
        v.y = isnan(v.y) ? 0.0f : v.y;
        v.z = isnan(v.z) ? 0.0f : v.z;
        v.w = isnan(v.w) ? 0.0f : v.w;
        out[i] = v;
    }
}

// -------- prep seq (NaN->bos) + new positions: no deps, no wait --------
__global__ void prep_pos_kernel(const float* __restrict__ seq,
                                const float* __restrict__ bos,
                                const int* __restrict__ positions,
                                float* __restrict__ out_seq,
                                float* __restrict__ out_pos)
{
    if (blockIdx.x < 4) {
        int i = blockIdx.x * 256 + threadIdx.x;
        float v = seq[i];
        out_seq[i] = isnan(v) ? bos[i & (INDIM - 1)] : v;
    } else {
        int i = threadIdx.x;
        if (i < NL * B) out_pos[i] = (float)(positions[i] + T);
    }
}

// ======== GEMM: Y[32,N] = X[32,K] @ W[N,K]^T ========
// cp.async 3-stage pipeline, f32x2 compute. PDL: W prefetch BEFORE the
// grid-dependency wait (weights are launch-independent), X after.
template<int KSPLIT>
__global__ void gemv_kernel(const float* __restrict__ X,
                            const float* __restrict__ W,
                            float* __restrict__ Y,
                            float* __restrict__ part,
                            int K, int N)
{
    __shared__ __align__(16) float Xs[DEPTH][32][36];
    __shared__ __align__(16) float Ws[DEPTH][64][36];

    const int t    = threadIdx.x;
    const int lane = t & 31;
    const int c0   = (t >> 5) * 8;
    const int n0   = blockIdx.x * 64;
    const int Kc   = K / KSPLIT;
    const int kbase = blockIdx.y * Kc;
    const int nch  = Kc >> 5;

    const int xrow = t >> 3, xk4 = (t & 7) * 4;
    const int wrow = t >> 2, wk  = (t & 3) * 8;

    const float* xsrc = X + (size_t)xrow * K + kbase + xk4;
    const float* wsrc = W + (size_t)(n0 + wrow) * K + kbase + wk;

    const unsigned xbase = (unsigned)__cvta_generic_to_shared(&Xs[0][0][0])
                         + (unsigned)((xrow * 36 + xk4) * 4);
    const unsigned wbase = (unsigned)__cvta_generic_to_shared(&Ws[0][0][0])
                         + (unsigned)((wrow * 36 + wk) * 4);
    const unsigned XST = 32 * 36 * 4;
    const unsigned WST = 64 * 36 * 4;

    // W prefetch for stages 0..DEPTH-2 — independent of predecessor
    #pragma unroll
    for (int p = 0; p < DEPTH - 1; p++) {
        if (p < nch) {
            cpa16(wbase + p * WST, wsrc + (size_t)p * 32);
            cpa16(wbase + p * WST + 16, wsrc + (size_t)p * 32 + 4);
        }
    }
    GDW();   // predecessor output (X) now valid
    // X for stage 0 joins the W group; X for stage 1 its own group
    if (0 < nch) cpa16(xbase, xsrc);
    CP_COMMIT();
    if (1 < nch) cpa16(xbase + XST, xsrc + 32);
    CP_COMMIT();

    unsigned long long acc[8];
    #pragma unroll
    for (int c = 0; c < 8; c++) acc[c] = 0ULL;

    int st = 0;
    int si = (DEPTH - 1) % DEPTH;
    for (int ch = 0; ch < nch; ch++) {
        CP_WAIT1();
        __syncthreads();

        #pragma unroll
        for (int p = 0; p < 16; p += 2) {
            unsigned long long x0 = *(const unsigned long long*)&Xs[st][lane][2 * p];
            unsigned long long x1 = *(const unsigned long long*)&Xs[st][lane][2 * p + 2];
            #pragma unroll
            for (int c = 0; c < 8; c++) {
                longlong2 w = *(const longlong2*)&Ws[st][c0 + c][2 * p];
                fma2(acc[c], x0, (unsigned long long)w.x);
                fma2(acc[c], x1, (unsigned long long)w.y);
            }
        }
        __syncthreads();

        int nc = ch + DEPTH - 1;
        if (nc < nch) {
            cpa16(xbase + si * XST, xsrc + (size_t)nc * 32);
            cpa16(wbase + si * WST, wsrc + (size_t)nc * 32);
            cpa16(wbase + si * WST + 16, wsrc + (size_t)nc * 32 + 4);
        }
        CP_COMMIT();
        st = (st == DEPTH - 1) ? 0 : st + 1;
        si = (si == DEPTH - 1) ? 0 : si + 1;
    }

    if (KSPLIT == 1) {
        #pragma unroll
        for (int c = 0; c < 8; c++) {
            float2 p = upk(acc[c]);
            Y[(size_t)lane * N + n0 + c0 + c] = p.x + p.y;
        }
    } else {
        float* pp = part + ((size_t)blockIdx.y * 32 + lane) * N + n0 + c0;
        #pragma unroll
        for (int c = 0; c < 8; c++) {
            float2 p = upk(acc[c]);
            pp[c] = p.x + p.y;
        }
    }
}

// sum split-K partials + gelu (l1 path)
template<int KS>
__global__ void reduce_gelu_kernel(const float* __restrict__ part,
                                   float* __restrict__ Y, int N)
{
    GDW();
    int i = blockIdx.x * 256 + threadIdx.x;
    if (i >= 32 * N) return;
    int r = i / N, n = i - r * N;
    float s = 0.f;
    #pragma unroll
    for (int k = 0; k < KS; k++) s += part[((size_t)k * 32 + r) * N + n];
    Y[i] = 0.5f * s * (1.0f + erff(s * 0.70710678118654752f));
}

// -------- fused qkv split-K(4) reduce + RoPE + cache scatter --------
__global__ void reduce_rope_kernel(const float* __restrict__ part,
                                   const int* __restrict__ pos_l,
                                   float* __restrict__ qout,
                                   float* __restrict__ kcache,
                                   float* __restrict__ vcache)
{
    int id = blockIdx.x * 256 + threadIdx.x;  // 49152 pairs
    int tok = id / 1536;
    int f   = (id - tok * 1536) * 2;
    int b = tok >> 2, t = tok & 3;
    int pos = pos_l[b];           // independent of predecessor
    GDW();
    float s0 = 0.f, s1 = 0.f;
    #pragma unroll
    for (int k = 0; k < 4; k++) {
        const float* p = part + ((size_t)(k * 32 + tok) * 3072) + f;
        s0 += p[0];
        s1 += p[1];
    }
    if (f < E) {
        int j = (f & 63) >> 1;
        float freq = __expf(-(float)j * (logf(10000.0f) / 32.0f));
        float sn, cs;
        sincosf((float)(pos + t) * freq, &sn, &cs);
        qout[(size_t)tok * E + f]     = s0 * cs - s1 * sn;
        qout[(size_t)tok * E + f + 1] = s0 * sn + s1 * cs;
    } else if (f < 2 * E) {
        int fk = f - E;
        int j = (fk & 63) >> 1;
        float freq = __expf(-(float)j * (logf(10000.0f) / 32.0f));
        float sn, cs;
        sincosf((float)(pos + t) * freq, &sn, &cs);
        int slot = (pos + t) % L;
        size_t off = ((size_t)b * L + slot) * E + fk;
        kcache[off]     = s0 * cs - s1 * sn;
        kcache[off + 1] = s0 * sn + s1 * cs;
    } else {
        int fv = f - 2 * E;
        int slot = (pos + t) % L;
        size_t off = ((size_t)b * L + slot) * E + fv;
        vcache[off]     = s0;
        vcache[off + 1] = s1;
    }
}

// -------- LayerNorm (layer-0 entry): w/b loaded before the wait --------
__global__ void ln_kernel(const float* __restrict__ X,
                          const float* __restrict__ w,
                          const float* __restrict__ b,
                          float* __restrict__ Y)
{
    int tok = blockIdx.x;
    int tid = threadIdx.x;
    float wv[4], bv[4];
    #pragma unroll
    for (int j = 0; j < 4; j++) { wv[j] = w[tid + 256 * j]; bv[j] = b[tid + 256 * j]; }
    GDW();
    const float* x = X + (size_t)tok * E;
    float v[4];
    #pragma unroll
    for (int j = 0; j < 4; j++) v[j] = x[tid + 256 * j];
    float s = v[0] + v[1] + v[2] + v[3];
    #pragma unroll
    for (int o = 16; o > 0; o >>= 1) s += __shfl_xor_sync(0xffffffffu, s, o);
    __shared__ float ws[8];
    if ((tid & 31) == 0) ws[tid >> 5] = s;
    __syncthreads();
    float mean = (ws[0]+ws[1]+ws[2]+ws[3]+ws[4]+ws[5]+ws[6]+ws[7]) * (1.0f / E);
    float s2 = 0.f;
    #pragma unroll
    for (int j = 0; j < 4; j++) { float d = v[j] - mean; s2 += d * d; }
    #pragma unroll
    for (int o = 16; o > 0; o >>= 1) s2 += __shfl_xor_sync(0xffffffffu, s2, o);
    __syncthreads();
    if ((tid & 31) == 0) ws[tid >> 5] = s2;
    __syncthreads();
    float var = (ws[0]+ws[1]+ws[2]+ws[3]+ws[4]+ws[5]+ws[6]+ws[7]) * (1.0f / E);
    float r = rsqrtf(var + 1e-5f);
    #pragma unroll
    for (int j = 0; j < 4; j++) {
        int idx = tid + 256 * j;
        Y[(size_t)tok * E + idx] = (v[j] - mean) * r * wv[j] + bv[j];
    }
}

// -------- fused: x += sum(8 partials); xn = LN(x) --------
__global__ void reduce_ln_kernel(const float* __restrict__ part,
                                 float* __restrict__ x,
                                 const float* __restrict__ w,
                                 const float* __restrict__ b,
                                 float* __restrict__ xn)
{
    int tok = blockIdx.x;
    int tid = threadIdx.x;
    float wv[4], bv[4];
    #pragma unroll
    for (int j = 0; j < 4; j++) { wv[j] = w[tid + 256 * j]; bv[j] = b[tid + 256 * j]; }
    GDW();
    float v[4];
    #pragma unroll
    for (int j = 0; j < 4; j++) {
        int idx = tid + 256 * j;
        float p = 0.f;
        #pragma unroll
        for (int k = 0; k < 8; k++) p += part[((size_t)(k * 32 + tok)) * E + idx];
        float xv = x[(size_t)tok * E + idx] + p;
        x[(size_t)tok * E + idx] = xv;
        v[j] = xv;
    }
    float s = v[0] + v[1] + v[2] + v[3];
    #pragma unroll
    for (int o = 16; o > 0; o >>= 1) s += __shfl_xor_sync(0xffffffffu, s, o);
    __shared__ float ws[8];
    if ((tid & 31) == 0) ws[tid >> 5] = s;
    __syncthreads();
    float mean = (ws[0]+ws[1]+ws[2]+ws[3]+ws[4]+ws[5]+ws[6]+ws[7]) * (1.0f / E);
    float s2 = 0.f;
    #pragma unroll
    for (int j = 0; j < 4; j++) { float d = v[j] - mean; s2 += d * d; }
    #pragma unroll
    for (int o = 16; o > 0; o >>= 1) s2 += __shfl_xor_sync(0xffffffffu, s2, o);
    __syncthreads();
    if ((tid & 31) == 0) ws[tid >> 5] = s2;
    __syncthreads();
    float var = (ws[0]+ws[1]+ws[2]+ws[3]+ws[4]+ws[5]+ws[6]+ws[7]) * (1.0f / E);
    float r = rsqrtf(var + 1e-5f);
    #pragma unroll
    for (int j = 0; j < 4; j++) {
        int idx = tid + 256 * j;
        xn[(size_t)tok * E + idx] = (v[j] - mean) * r * wv[j] + bv[j];
    }
}

// -------- fused: x += partials; out_x = LN(x); eos dot --------
__global__ void reduce_ln_eos_kernel(const float* __restrict__ part,
                                     float* __restrict__ x,
                                     const float* __restrict__ w,
                                     const float* __restrict__ b,
                                     const float* __restrict__ ew,
                                     const float* __restrict__ eb,
                                     float* __restrict__ Y,
                                     float* __restrict__ out_eos)
{
    int tok = blockIdx.x;
    int tid = threadIdx.x;
    float wv[4], bv[4], ev[4];
    #pragma unroll
    for (int j = 0; j < 4; j++) {
        wv[j] = w[tid + 256 * j];
        bv[j] = b[tid + 256 * j];
        ev[j] = ew[tid + 256 * j];
    }
    GDW();
    float v[4];
    #pragma unroll
    for (int j = 0; j < 4; j++) {
        int idx = tid + 256 * j;
        float p = 0.f;
        #pragma unroll
        for (int k = 0; k < 8; k++) p += part[((size_t)(k * 32 + tok)) * E + idx];
        v[j] = x[(size_t)tok * E + idx] + p;
    }
    float s = v[0] + v[1] + v[2] + v[3];
    #pragma unroll
    for (int o = 16; o > 0; o >>= 1) s += __shfl_xor_sync(0xffffffffu, s, o);
    __shared__ float ws[8];
    if ((tid & 31) == 0) ws[tid >> 5] = s;
    __syncthreads();
    float mean = (ws[0]+ws[1]+ws[2]+ws[3]+ws[4]+ws[5]+ws[6]+ws[7]) * (1.0f / E);
    float s2 = 0.f;
    #pragma unroll
    for (int j = 0; j < 4; j++) { float d = v[j] - mean; s2 += d * d; }
    #pragma unroll
    for (int o = 16; o > 0; o >>= 1) s2 += __shfl_xor_sync(0xffffffffu, s2, o);
    __syncthreads();
    if ((tid & 31) == 0) ws[tid >> 5] = s2;
    __syncthreads();
    float var = (ws[0]+ws[1]+ws[2]+ws[3]+ws[4]+ws[5]+ws[6]+ws[7]) * (1.0f / E);
    float r = rsqrtf(var + 1e-5f);
    float ed = 0.f;
    #pragma unroll
    for (int j = 0; j < 4; j++) {
        int idx = tid + 256 * j;
        float y = (v[j] - mean) * r * wv[j] + bv[j];
        Y[(size_t)tok * E + idx] = y;
        ed += y * ev[j];
    }
    #pragma unroll
    for (int o = 16; o > 0; o >>= 1) ed += __shfl_xor_sync(0xffffffffu, ed, o);
    __syncthreads();
    if ((tid & 31) == 0) ws[tid >> 5] = ed;
    __syncthreads();
    if (tid == 0)
        out_eos[tok] = ws[0]+ws[1]+ws[2]+ws[3]+ws[4]+ws[5]+ws[6]+ws[7] + eb[0];
}

// -------- Attention partial: grid 512, K/V from output cache --------
#define CMAX 260
__global__ void attn_part_kernel(const float* __restrict__ q,
                                 const float* __restrict__ kc,
                                 const float* __restrict__ vc,
                                 const int* __restrict__ pos_l,
                                 float* __restrict__ po,
                                 float* __restrict__ gm,
                                 float* __restrict__ gl)
{
    __shared__ float qs[4][64];
    __shared__ float sc[4][CMAX];
    __shared__ float red[8];
    __shared__ float mt[4], lt[4];
    __shared__ float vpart[4][4][64];

    int bh   = blockIdx.x & 127;
    int cidx = blockIdx.x >> 7;
    int b = bh >> 4, h = bh & 15;
    int tid = threadIdx.x;
    int pos = pos_l[b];
    GDW();
    int slen = pos + T;
    int chunk = (slen + 3) >> 2;
    int s0 = cidx * chunk;
    int s1 = min(slen, s0 + chunk);
    int len = s1 - s0;
    int gbase = (bh * 4 + cidx) * 4;

    if (len <= 0) {
        po[(size_t)gbase * 64 + tid] = 0.f;
        if (tid < 4) { gm[gbase + tid] = -1e30f; gl[gbase + tid] = 0.f; }
        return;
    }

    {
        int t = tid >> 6, d = tid & 63;
        qs[t][d] = q[((size_t)(b * T + t) * E) + h * D + d];
    }
    __syncthreads();

    const float scale = 0.125f;
    for (int i = tid; i < len; i += 256) {
        int s = s0 + i;
        const float4* kr = (const float4*)(kc + ((size_t)b * L + s) * E + h * D);
        float d0 = 0.f, d1 = 0.f, d2 = 0.f, d3 = 0.f;
        #pragma unroll
        for (int i4 = 0; i4 < 16; i4++) {
            float4 kv = kr[i4];
            int d = i4 * 4;
            d0 += qs[0][d]*kv.x + qs[0][d+1]*kv.y + qs[0][d+2]*kv.z + qs[0][d+3]*kv.w;
            d1 += qs[1][d]*kv.x + qs[1][d+1]*kv.y + qs[1][d+2]*kv.z + qs[1][d+3]*kv.w;
            d2 += qs[2][d]*kv.x + qs[2][d+1]*kv.y + qs[2][d+2]*kv.z + qs[2][d+3]*kv.w;
            d3 += qs[3][d]*kv.x + qs[3][d+1]*kv.y + qs[3][d+2]*kv.z + qs[3][d+3]*kv.w;
        }
        sc[0][i] = (s <= pos + 0) ? d0 * scale : -1e30f;
        sc[1][i] = (s <= pos + 1) ? d1 * scale : -1e30f;
        sc[2][i] = (s <= pos + 2) ? d2 * scale : -1e30f;
        sc[3][i] = (s <= pos + 3) ? d3 * scale : -1e30f;
    }
    __syncthreads();

    #pragma unroll
    for (int t = 0; t < 4; t++) {
        float m = -1e30f;
        for (int i = tid; i < len; i += 256) m = fmaxf(m, sc[t][i]);
        #pragma unroll
        for (int o = 16; o > 0; o >>= 1) m = fmaxf(m, __shfl_xor_sync(0xffffffffu, m, o));
        if ((tid & 31) == 0) red[tid >> 5] = m;
        __syncthreads();
        m = fmaxf(fmaxf(fmaxf(red[0], red[1]), fmaxf(red[2], red[3])),
                  fmaxf(fmaxf(red[4], red[5]), fmaxf(red[6], red[7])));
        float ssum = 0.f;
        for (int i = tid; i < len; i += 256) {
            float e = __expf(sc[t][i] - m);
            sc[t][i] = e;
            ssum += e;
        }
        #pragma unroll
        for (int o = 16; o > 0; o >>= 1) ssum += __shfl_xor_sync(0xffffffffu, ssum, o);
        __syncthreads();
        if ((tid & 31) == 0) red[tid >> 5] = ssum;
        __syncthreads();
        if (tid == 0) {
            mt[t] = m;
            lt[t] = red[0]+red[1]+red[2]+red[3]+red[4]+red[5]+red[6]+red[7];
        }
        __syncthreads();
    }

    {
        int sg = tid >> 6, d = tid & 63;
        int q4 = (len + 3) >> 2;
        int i0 = sg * q4;
        int i1 = min(len, i0 + q4);
        const float* vp = vc + ((size_t)b * L + s0) * E + h * D + d;
        float a0 = 0.f, a1 = 0.f, a2 = 0.f, a3 = 0.f;
        int i = i0;
        for (; i + 2 <= i1; i += 2) {
            float v0 = vp[(size_t)i * E];
            float v1 = vp[(size_t)(i + 1) * E];
            a0 += sc[0][i] * v0 + sc[0][i+1] * v1;
            a1 += sc[1][i] * v0 + sc[1][i+1] * v1;
            a2 += sc[2][i] * v0 + sc[2][i+1] * v1;
            a3 += sc[3][i] * v0 + sc[3][i+1] * v1;
        }
        if (i < i1) {
            float v0 = vp[(size_t)i * E];
            a0 += sc[0][i] * v0;
            a1 += sc[1][i] * v0;
            a2 += sc[2][i] * v0;
            a3 += sc[3][i] * v0;
        }
        vpart[sg][0][d] = a0;
        vpart[sg][1][d] = a1;
        vpart[sg][2][d] = a2;
        vpart[sg][3][d] = a3;
    }
    __syncthreads();
    {
        int t = tid >> 6, d = tid & 63;
        float sum = vpart[0][t][d] + vpart[1][t][d] + vpart[2][t][d] + vpart[3][t][d];
        po[((size_t)(gbase + t)) * 64 + d] = sum;
        if (tid < 4) { gm[gbase + tid] = mt[tid]; gl[gbase + tid] = lt[tid]; }
    }
}

// -------- Attention combine --------
__global__ void attn_comb_kernel(const float* __restrict__ po,
                                 const float* __restrict__ gm,
                                 const float* __restrict__ gl,
                                 float* __restrict__ out)
{
    GDW();
    int bh = blockIdx.x;
    int b = bh >> 4, h = bh & 15;
    int tid = threadIdx.x;
    int t = tid >> 6, d = tid & 63;

    float m0 = gm[(bh * 4 + 0) * 4 + t];
    float m1 = gm[(bh * 4 + 1) * 4 + t];
    float m2 = gm[(bh * 4 + 2) * 4 + t];
    float m3 = gm[(bh * 4 + 3) * 4 + t];
    float M = fmaxf(fmaxf(m0, m1), fmaxf(m2, m3));
    float w0 = __expf(m0 - M), w1 = __expf(m1 - M);
    float w2 = __expf(m2 - M), w3 = __expf(m3 - M);
    float l = w0 * gl[(bh * 4 + 0) * 4 + t] + w1 * gl[(bh * 4 + 1) * 4 + t]
            + w2 * gl[(bh * 4 + 2) * 4 + t] + w3 * gl[(bh * 4 + 3) * 4 + t];
    float o = w0 * po[((size_t)(bh * 4 + 0) * 4 + t) * 64 + d]
            + w1 * po[((size_t)(bh * 4 + 1) * 4 + t) * 64 + d]
            + w2 * po[((size_t)(bh * 4 + 2) * 4 + t) * 64 + d]
            + w3 * po[((size_t)(bh * 4 + 3) * 4 + t) * 64 + d];
    out[((size_t)(b * T + t) * E) + h * D + d] = o / l;
}

// -------- host: PDL launch helper --------
template<typename F, typename... Args>
static inline void pdl(dim3 g, dim3 blk, F f, Args... args)
{
    cudaLaunchAttribute at[1];
    at[0].id = cudaLaunchAttributeProgrammaticStreamSerialization;
    at[0].val.programmaticStreamSerializationAllowed = 1;
    cudaLaunchConfig_t cfg = {};
    cfg.gridDim = g;
    cfg.blockDim = blk;
    cfg.dynamicSmemBytes = 0;
    cfg.stream = 0;
    cfg.attrs = at;
    cfg.numAttrs = 1;
    cudaLaunchKernelEx(&cfg, f, args...);
}

extern "C" void kernel_launch(void* const* d_in, const int* in_sizes, int n_in,
                              void* d_out, int out_size)
{
    const float* seq       = (const float*)d_in[0];
    const float* bos       = (const float*)d_in[1];
    const float* caches    = (const float*)d_in[2];
    const int*   positions = (const int*)  d_in[3];
    const float* in_w      = (const float*)d_in[4];
    const float* ip_w      = (const float*)d_in[5];
    const float* op_w      = (const float*)d_in[6];
    const float* n1w       = (const float*)d_in[7];
    const float* n1b       = (const float*)d_in[8];
    const float* n2w       = (const float*)d_in[9];
    const float* n2b       = (const float*)d_in[10];
    const float* l1_w      = (const float*)d_in[11];
    const float* l2_w      = (const float*)d_in[12];
    const float* on_w      = (const float*)d_in[13];
    const float* on_b      = (const float*)d_in[14];
    const float* eos_w     = (const float*)d_in[15];
    const float* eos_b     = (const float*)d_in[16];

    float* out = (float*)d_out;
    const size_t cache_elems = (size_t)NL * 2 * B * L * E;
    float* out_x     = out;
    float* out_eos   = out + (size_t)NTOK * E;
    float* out_cache = out_eos + NTOK;
    float* out_pos   = out_cache + cache_elems;

    float *px, *pxn, *pq, *pattn, *ph, *pseq, *ppart, *ppo, *pm, *pl;
    cudaGetSymbolAddress((void**)&px,    g_x);
    cudaGetSymbolAddress((void**)&pxn,   g_xn);
    cudaGetSymbolAddress((void**)&pq,    g_q);
    cudaGetSymbolAddress((void**)&pattn, g_attn);
    cudaGetSymbolAddress((void**)&ph,    g_h);
    cudaGetSymbolAddress((void**)&pseq,  g_seq);
    cudaGetSymbolAddress((void**)&ppart, g_part);
    cudaGetSymbolAddress((void**)&ppo,   g_po);
    cudaGetSymbolAddress((void**)&pm,    g_m);
    cudaGetSymbolAddress((void**)&pl,    g_l);

    long nf4 = (long)(cache_elems / 4);
    cache_copy_kernel<<<(unsigned)((nf4 + 255) / 256), 256>>>((const float4*)caches,
                                                              (float4*)out_cache, nf4);

    pdl(dim3(5), dim3(256), prep_pos_kernel, seq, bos, positions, pseq, out_pos);
    pdl(dim3(E / 64, 1), dim3(256), gemv_kernel<1>,
        (const float*)pseq, in_w, px, (float*)nullptr, (int)INDIM, (int)E);
    pdl(dim3(NTOK), dim3(256), ln_kernel, (const float*)px, n1w, n1b, pxn);

    for (int i = 0; i < NL; i++) {
        const float* ipw = ip_w + (size_t)i * 3 * E * E;
        const float* opw = op_w + (size_t)i * E * E;
        const float* l1  = l1_w + (size_t)i * FF * E;
        const float* l2  = l2_w + (size_t)i * E * FF;
        float* kcache = out_cache + ((size_t)i * 2 + 0) * B * L * E;
        float* vcache = out_cache + ((size_t)i * 2 + 1) * B * L * E;
        const int* posl = positions + i * B;

        // qkv: K=1024, N=3072, split-K=4 -> 192 blocks
        pdl(dim3(3 * E / 64, 4), dim3(256), gemv_kernel<4>,
            (const float*)pxn, ipw, (float*)nullptr, ppart, (int)E, (int)(3 * E));
        pdl(dim3(192), dim3(256), reduce_rope_kernel,
            (const float*)ppart, posl, pq, kcache, vcache);

        pdl(dim3(512), dim3(256), attn_part_kernel,
            (const float*)pq, (const float*)kcache, (const float*)vcache, posl,
            ppo, pm, pl);
        pdl(dim3(B * H), dim3(256), attn_comb_kernel,
            (const float*)ppo, (const float*)pm, (const float*)pl, pattn);

        // op: K=1024, N=1024, split-K=8 -> 128 blocks; fused reduce+add+LN
        pdl(dim3(E / 64, 8), dim3(256), gemv_kernel<8>,
            (const float*)pattn, opw, (float*)nullptr, ppart, (int)E, (int)E);
        pdl(dim3(NTOK), dim3(256), reduce_ln_kernel,
            (const float*)ppart, px, n2w + (size_t)i * E, n2b + (size_t)i * E, pxn);

        // l1: K=1024, N=4096, split-K=2 -> 128 blocks; gelu in reduce
        pdl(dim3(FF / 64, 2), dim3(256), gemv_kernel<2>,
            (const float*)pxn, l1, (float*)nullptr, ppart, (int)E, (int)FF);
        pdl(dim3((32 * FF + 255) / 256), dim3(256), reduce_gelu_kernel<2>,
            (const float*)ppart, ph, (int)FF);

        // l2: K=4096, N=1024, split-K=8 -> 128 blocks; fused reduce+add+LN/eos
        pdl(dim3(E / 64, 8), dim3(256), gemv_kernel<8>,
            (const float*)ph, l2, (float*)nullptr, ppart, (int)FF, (int)E);
        if (i + 1 < NL) {
            pdl(dim3(NTOK), dim3(256), reduce_ln_kernel,
                (const float*)ppart, px,
                n1w + (size_t)(i + 1) * E, n1b + (size_t)(i + 1) * E, pxn);
        } else {
            pdl(dim3(NTOK), dim3(256), reduce_ln_eos_kernel,
                (const float*)ppart, px, on_w, on_b, eos_w, eos_b,
                out_x, out_eos);
        }
    }
}